// round 1
// baseline (speedup 1.0000x reference)
#include <cuda_runtime.h>
#include <math.h>

#define Bx  32
#define Wt  256
#define IND 4096
#define Hd  1024
#define Zd  100
#define Dd  100
#define G3  3072
#define ZH  1124
#define NB  128

// ---------------- device globals (scratch; no runtime allocation) ----------------
__device__ float g_gi[25165824];        // [W*B][3H]  (m = w*32+b, row-major over gate cols) ~100MB
__device__ float g_h4T[2 * Hd * Bx];    // ping-pong h, packed: [k>>2][b][k&3]
__device__ float g_zT[Zd * Bx];         // z_t transposed [z][b]
__device__ float g_zpreT[Zd * Bx];      // z before planar flow
__device__ float g_Wmd[Zd * ZH];        // Wmu @ Wd
__device__ float g_Wsd[Zd * ZH];        // Wsig @ Wd
__device__ float g_bmu2[Zd];
__device__ float g_bsig2[Zd];
__device__ unsigned g_cnt;              // zero-init; invariant restored each launch
__device__ unsigned g_gen;

// ---------------- grid-wide barrier (128 resident CTAs) ----------------
__device__ __forceinline__ void grid_barrier() {
    __syncthreads();
    if (threadIdx.x == 0) {
        __threadfence();                        // flush my writes (CCTL.IVALL on sm_103a)
        unsigned gen = *(volatile unsigned*)&g_gen;
        if (atomicAdd(&g_cnt, 1u) == NB - 1u) {
            g_cnt = 0u;
            __threadfence();
            atomicAdd(&g_gen, 1u);
        } else {
            while (*(volatile unsigned*)&g_gen == gen) { }
        }
        __threadfence();                        // invalidate L1 so we see peers' writes
    }
    __syncthreads();
}

// ---------------- prep: fuse dense layer into mu/sigma heads ----------------
__global__ void prep_kernel(const float* __restrict__ Wd, const float* __restrict__ bd,
                            const float* __restrict__ Wmu, const float* __restrict__ bmu,
                            const float* __restrict__ Wsig, const float* __restrict__ bsig)
{
    int idx = blockIdx.x * blockDim.x + threadIdx.x;
    if (idx < Zd * ZH) {
        int q = idx / ZH, j = idx % ZH;
        float am = 0.f, as = 0.f;
        for (int d = 0; d < Dd; d++) {
            float wd = Wd[(size_t)d * ZH + j];
            am = fmaf(Wmu[q * Dd + d], wd, am);
            as = fmaf(Wsig[q * Dd + d], wd, as);
        }
        g_Wmd[idx] = am;
        g_Wsd[idx] = as;
    }
    if (idx < Zd) {
        float am = bmu[idx], as = bsig[idx];
        for (int d = 0; d < Dd; d++) {
            am = fmaf(Wmu[idx * Dd + d], bd[d], am);
            as = fmaf(Wsig[idx * Dd + d], bd[d], as);
        }
        g_bmu2[idx] = am;
        g_bsig2[idx] = as;
    }
}

// ---------------- kernel A: gi[w*32+b][g] = x[b][w][:] . W_ih[g][:] + b_ih[g] ----------------
// M=8192, N=3072, K=4096.  BM=BN=128, BK=16, 256 threads, 8x8 per thread.
__global__ void __launch_bounds__(256) gemm_xw(const float* __restrict__ x,
                                               const float* __restrict__ Wih,
                                               const float* __restrict__ bih)
{
    __shared__ float As[16][132];
    __shared__ float Bs[16][132];
    const int tid = threadIdx.x;
    const int bn = blockIdx.x * 128;
    const int bm = blockIdx.y * 128;
    const int tx = tid & 15, ty = tid >> 4;
    const int lr = tid >> 2, lk = (tid & 3) << 2;

    const float* arow0;
    const float* arow1;
    {
        int m0 = bm + lr;      int w0 = m0 >> 5, b0 = m0 & 31;
        int m1 = bm + lr + 64; int w1 = m1 >> 5, b1 = m1 & 31;
        arow0 = x + (size_t)(b0 * Wt + w0) * IND + lk;
        arow1 = x + (size_t)(b1 * Wt + w1) * IND + lk;
    }
    const float* brow0 = Wih + (size_t)(bn + lr) * IND + lk;
    const float* brow1 = Wih + (size_t)(bn + lr + 64) * IND + lk;

    float acc[8][8];
    #pragma unroll
    for (int i = 0; i < 8; i++)
        #pragma unroll
        for (int j = 0; j < 8; j++) acc[i][j] = 0.f;

    for (int k0 = 0; k0 < IND; k0 += 16) {
        float4 a0 = *(const float4*)(arow0 + k0);
        float4 a1 = *(const float4*)(arow1 + k0);
        float4 b0 = *(const float4*)(brow0 + k0);
        float4 b1 = *(const float4*)(brow1 + k0);
        __syncthreads();
        As[lk + 0][lr] = a0.x; As[lk + 1][lr] = a0.y; As[lk + 2][lr] = a0.z; As[lk + 3][lr] = a0.w;
        As[lk + 0][lr + 64] = a1.x; As[lk + 1][lr + 64] = a1.y; As[lk + 2][lr + 64] = a1.z; As[lk + 3][lr + 64] = a1.w;
        Bs[lk + 0][lr] = b0.x; Bs[lk + 1][lr] = b0.y; Bs[lk + 2][lr] = b0.z; Bs[lk + 3][lr] = b0.w;
        Bs[lk + 0][lr + 64] = b1.x; Bs[lk + 1][lr + 64] = b1.y; Bs[lk + 2][lr + 64] = b1.z; Bs[lk + 3][lr + 64] = b1.w;
        __syncthreads();
        #pragma unroll
        for (int k = 0; k < 16; k++) {
            float af[8], bf[8];
            *(float4*)(af)     = *(const float4*)&As[k][ty * 8];
            *(float4*)(af + 4) = *(const float4*)&As[k][ty * 8 + 4];
            *(float4*)(bf)     = *(const float4*)&Bs[k][tx * 8];
            *(float4*)(bf + 4) = *(const float4*)&Bs[k][tx * 8 + 4];
            #pragma unroll
            for (int i = 0; i < 8; i++)
                #pragma unroll
                for (int j = 0; j < 8; j++)
                    acc[i][j] = fmaf(af[i], bf[j], acc[i][j]);
        }
    }

    #pragma unroll
    for (int i = 0; i < 8; i++) {
        int m = bm + ty * 8 + i;
        float* orow = g_gi + (size_t)m * G3 + bn + tx * 8;
        #pragma unroll
        for (int j = 0; j < 8; j += 4) {
            float4 v;
            v.x = acc[i][j + 0] + bih[bn + tx * 8 + j + 0];
            v.y = acc[i][j + 1] + bih[bn + tx * 8 + j + 1];
            v.z = acc[i][j + 2] + bih[bn + tx * 8 + j + 2];
            v.w = acc[i][j + 3] + bih[bn + tx * 8 + j + 3];
            *(float4*)(orow + j) = v;
        }
    }
}

// ---------------- persistent recurrence kernel ----------------
// Block bk owns hidden indices i in [bk*8, bk*8+8); warp w -> i = bk*8 + w, and all
// three gate columns {i, H+i, 2H+i}  ->  h_new computed in-register, no extra barrier.
#define SMEM_FLOATS (24 * 1024 + 1124 + 1124 + 128 + 512)
#define SMEM_BYTES  (SMEM_FLOATS * 4)

__global__ void __launch_bounds__(256) recur_kernel(
    const float* __restrict__ Whh, const float* __restrict__ bhh,
    const float* __restrict__ u, const float* __restrict__ Wpnf,
    const float* __restrict__ bpnf, const float* __restrict__ noise,
    float* __restrict__ out)
{
    extern __shared__ float sm[];
    float* s_whh = sm;                       // 24*1024 : rows (w*3+gate) of W_hh
    float* s_wmd = sm + 24 * 1024;           // 1124
    float* s_wsd = s_wmd + 1124;             // 1124
    float* s_pnf = s_wsd + 1124;             // 128 (100 used)
    float* s_red = s_pnf + 128;              // 8 warps * 2 * 32

    const int bk = blockIdx.x;
    const int tid = threadIdx.x;
    const int lane = tid & 31;
    const int wp = tid >> 5;
    const int i0 = bk * 8;

    for (int idx = tid; idx < 24 * 1024; idx += 256) {
        int r = idx >> 10, k = idx & 1023;
        int ww = r / 3, gate = r % 3;
        s_whh[idx] = Whh[(size_t)(gate * Hd + i0 + ww) * Hd + k];
    }
    if (bk < Zd) {
        for (int j = tid; j < ZH; j += 256) {
            s_wmd[j] = g_Wmd[bk * ZH + j];
            s_wsd[j] = g_Wsd[bk * ZH + j];
        }
        for (int j = tid; j < Zd; j += 256) s_pnf[j] = Wpnf[bk * Zd + j];
    }
    g_h4T[bk * 256 + tid] = 0.f;                                   // zero h buffer 0
    if (bk == 0) for (int j = tid; j < Zd * Bx; j += 256) g_zT[j] = 0.f;

    const int i = i0 + wp;
    const float bhr = bhh[i];
    const float bhz = bhh[Hd + i];
    const float bhn = bhh[2 * Hd + i];
    const float u0 = u[0];
    const float bpq = (bk < Zd) ? bpnf[bk] : 0.f;
    const float bm2 = (bk < Zd) ? g_bmu2[bk] : 0.f;
    const float bs2 = (bk < Zd) ? g_bsig2[bk] : 0.f;

    float* out_z  = out;
    float* out_mu = out + Bx * Wt * Zd;
    float* out_lv = out + 2 * Bx * Wt * Zd;

    const float4* wr4 = (const float4*)(s_whh + (wp * 3 + 0) * Hd);
    const float4* wz4 = (const float4*)(s_whh + (wp * 3 + 1) * Hd);
    const float4* wn4 = (const float4*)(s_whh + (wp * 3 + 2) * Hd);
    const float4* wm4 = (const float4*)(s_wmd + Zd);
    const float4* ws4 = (const float4*)(s_wsd + Zd);

    grid_barrier();

    #pragma unroll 1
    for (int t = 0; t < Wt; t++) {
        // ---- phase 1: gh + gates + h_new (all 128 blocks) ----
        {
            const float* gip = g_gi + (size_t)(t * Bx + lane) * G3;
            float gir = gip[i], giz = gip[Hd + i], gin = gip[2 * Hd + i];
            const float4* hb = (const float4*)(g_h4T + (t & 1) * (Hd * Bx));
            float ar = 0.f, az = 0.f, an = 0.f;
            #pragma unroll 4
            for (int kq = 0; kq < 256; kq++) {
                float4 h4 = hb[kq * 32 + lane];
                float4 r4 = wr4[kq];
                float4 z4 = wz4[kq];
                float4 n4 = wn4[kq];
                ar = fmaf(h4.x, r4.x, ar); ar = fmaf(h4.y, r4.y, ar);
                ar = fmaf(h4.z, r4.z, ar); ar = fmaf(h4.w, r4.w, ar);
                az = fmaf(h4.x, z4.x, az); az = fmaf(h4.y, z4.y, az);
                az = fmaf(h4.z, z4.z, az); az = fmaf(h4.w, z4.w, az);
                an = fmaf(h4.x, n4.x, an); an = fmaf(h4.y, n4.y, an);
                an = fmaf(h4.z, n4.z, an); an = fmaf(h4.w, n4.w, an);
            }
            float rg = 1.f / (1.f + expf(-(gir + ar + bhr)));
            float zg = 1.f / (1.f + expf(-(giz + az + bhz)));
            float ng = tanhf(gin + rg * (an + bhn));
            int hidx = ((i >> 2) * 32 + lane) * 4 + (i & 3);
            float hold = g_h4T[(t & 1) * (Hd * Bx) + hidx];
            float hnew = (1.f - zg) * ng + zg * hold;
            g_h4T[((t + 1) & 1) * (Hd * Bx) + hidx] = hnew;
        }
        grid_barrier();

        // ---- phase 2: mu / logvar / z_pre (blocks 0..99; block = z-index q) ----
        if (bk < Zd) {
            float am = 0.f, as = 0.f;
            for (int z2 = wp; z2 < Zd; z2 += 8) {
                float zv = g_zT[z2 * 32 + lane];
                am = fmaf(zv, s_wmd[z2], am);
                as = fmaf(zv, s_wsd[z2], as);
            }
            const float4* hb2 = (const float4*)(g_h4T + ((t + 1) & 1) * (Hd * Bx));
            #pragma unroll 4
            for (int kq = wp * 32; kq < wp * 32 + 32; kq++) {
                float4 h4 = hb2[kq * 32 + lane];
                float4 m4 = wm4[kq];
                float4 s4 = ws4[kq];
                am = fmaf(h4.x, m4.x, am); am = fmaf(h4.y, m4.y, am);
                am = fmaf(h4.z, m4.z, am); am = fmaf(h4.w, m4.w, am);
                as = fmaf(h4.x, s4.x, as); as = fmaf(h4.y, s4.y, as);
                as = fmaf(h4.z, s4.z, as); as = fmaf(h4.w, s4.w, as);
            }
            s_red[(wp * 2 + 0) * 32 + lane] = am;
            s_red[(wp * 2 + 1) * 32 + lane] = as;
            __syncthreads();
            if (wp == 0) {
                float m = bm2, s = bs2;
                #pragma unroll
                for (int ww = 0; ww < 8; ww++) {
                    m += s_red[(ww * 2 + 0) * 32 + lane];
                    s += s_red[(ww * 2 + 1) * 32 + lane];
                }
                float lv = fmaxf(s, 0.f) + log1pf(expf(-fabsf(s)));   // softplus, stable
                float eps = noise[(size_t)(t * Bx + lane) * Zd + bk];
                float zp = m + expf(0.5f * lv) * eps;
                g_zpreT[bk * 32 + lane] = zp;
                out_mu[(size_t)(lane * Wt + t) * Zd + bk] = m;
                out_lv[(size_t)(lane * Wt + t) * Zd + bk] = lv;
            }
        }
        grid_barrier();

        // ---- phase 3: planar flow + outputs (blocks 0..99, warp 0) ----
        if (bk < Zd && wp == 0) {
            float a0 = 0.f, a1 = 0.f, a2 = 0.f, a3 = 0.f;
            for (int z2 = 0; z2 < Zd; z2 += 4) {
                a0 = fmaf(g_zpreT[(z2 + 0) * 32 + lane], s_pnf[z2 + 0], a0);
                a1 = fmaf(g_zpreT[(z2 + 1) * 32 + lane], s_pnf[z2 + 1], a1);
                a2 = fmaf(g_zpreT[(z2 + 2) * 32 + lane], s_pnf[z2 + 2], a2);
                a3 = fmaf(g_zpreT[(z2 + 3) * 32 + lane], s_pnf[z2 + 3], a3);
            }
            float zp = g_zpreT[bk * 32 + lane];
            float zn = zp + u0 * tanhf(((a0 + a1) + (a2 + a3)) + bpq);
            out_z[(size_t)(lane * Wt + t) * Zd + bk] = zn;
            g_zT[bk * 32 + lane] = zn;
        }
        grid_barrier();
    }
}

// ---------------- launch ----------------
extern "C" void kernel_launch(void* const* d_in, const int* in_sizes, int n_in,
                              void* d_out, int out_size)
{
    const float* x    = (const float*)d_in[0];
    const float* Wih  = (const float*)d_in[1];
    const float* Whh  = (const float*)d_in[2];
    const float* bih  = (const float*)d_in[3];
    const float* bhh  = (const float*)d_in[4];
    const float* Wd   = (const float*)d_in[5];
    const float* bd   = (const float*)d_in[6];
    const float* Wmu  = (const float*)d_in[7];
    const float* bmu  = (const float*)d_in[8];
    const float* Wsig = (const float*)d_in[9];
    const float* bsig = (const float*)d_in[10];
    const float* u    = (const float*)d_in[11];
    const float* Wpnf = (const float*)d_in[12];
    const float* bpnf = (const float*)d_in[13];
    const float* noise= (const float*)d_in[14];
    float* out = (float*)d_out;

    cudaFuncSetAttribute(recur_kernel, cudaFuncAttributeMaxDynamicSharedMemorySize, SMEM_BYTES);

    prep_kernel<<<(Zd * ZH + 255) / 256, 256>>>(Wd, bd, Wmu, bmu, Wsig, bsig);
    gemm_xw<<<dim3(G3 / 128, (Wt * Bx) / 128), 256>>>(x, Wih, bih);
    recur_kernel<<<NB, 256, SMEM_BYTES>>>(Whh, bhh, u, Wpnf, bpnf, noise, out);
}

// round 2
// speedup vs baseline: 1.2912x; 1.2912x over previous
#include <cuda_runtime.h>
#include <math.h>

#define Bx  32
#define Wt  256
#define IND 4096
#define Hd  1024
#define Zd  100
#define Dd  100
#define G3  3072
#define ZH  1124
#define NB  128

// ---------------- f32x2 packed-FMA helpers (sm_103a FFMA2) ----------------
__device__ __forceinline__ unsigned long long pack2(float lo, float hi) {
    unsigned long long r;
    asm("mov.b64 %0, {%1, %2};" : "=l"(r) : "f"(lo), "f"(hi));
    return r;
}
__device__ __forceinline__ void fma2(unsigned long long& d, unsigned long long a, unsigned long long b) {
    asm("fma.rn.f32x2 %0, %1, %2, %0;" : "+l"(d) : "l"(a), "l"(b));
}
__device__ __forceinline__ float2 unpack2(unsigned long long v) {
    float2 r;
    asm("mov.b64 {%0, %1}, %2;" : "=f"(r.x), "=f"(r.y) : "l"(v));
    return r;
}
__device__ __forceinline__ float hsum2(unsigned long long a, unsigned long long b) {
    float2 p = unpack2(a), q = unpack2(b);
    return (p.x + p.y) + (q.x + q.y);
}

// ---------------- device globals (scratch; no runtime allocation) ----------------
__device__ __align__(16) float g_gi[25165824];        // [W*B][3H]
__device__ __align__(16) float g_h4T[2 * Hd * Bx];    // ping-pong h, packed [k>>2][b][k&3]
__device__ __align__(16) float g_zT[Zd * Bx];         // z_t transposed [z][b]
__device__ __align__(16) float g_zpreT[Zd * Bx];      // z before planar flow
__device__ __align__(16) float g_Wmd[Zd * ZH];        // Wmu @ Wd
__device__ __align__(16) float g_Wsd[Zd * ZH];        // Wsig @ Wd
__device__ float g_bmu2[Zd];
__device__ float g_bsig2[Zd];
__device__ unsigned g_cnt;
__device__ unsigned g_gen;

// ---------------- grid-wide barrier (128 resident CTAs) ----------------
__device__ __forceinline__ void grid_barrier() {
    __syncthreads();
    if (threadIdx.x == 0) {
        __threadfence();
        unsigned gen = *(volatile unsigned*)&g_gen;
        if (atomicAdd(&g_cnt, 1u) == NB - 1u) {
            g_cnt = 0u;
            __threadfence();
            atomicAdd(&g_gen, 1u);
        } else {
            while (*(volatile unsigned*)&g_gen == gen) { }
        }
        __threadfence();
    }
    __syncthreads();
}

// ---------------- prep: fuse dense layer into mu/sigma heads ----------------
__global__ void prep_kernel(const float* __restrict__ Wd, const float* __restrict__ bd,
                            const float* __restrict__ Wmu, const float* __restrict__ bmu,
                            const float* __restrict__ Wsig, const float* __restrict__ bsig)
{
    int idx = blockIdx.x * blockDim.x + threadIdx.x;
    if (idx < Zd * ZH) {
        int q = idx / ZH, j = idx % ZH;
        float am = 0.f, as = 0.f;
        for (int d = 0; d < Dd; d++) {
            float wd = Wd[(size_t)d * ZH + j];
            am = fmaf(Wmu[q * Dd + d], wd, am);
            as = fmaf(Wsig[q * Dd + d], wd, as);
        }
        g_Wmd[idx] = am;
        g_Wsd[idx] = as;
    }
    if (idx < Zd) {
        float am = bmu[idx], as = bsig[idx];
        for (int d = 0; d < Dd; d++) {
            am = fmaf(Wmu[idx * Dd + d], bd[d], am);
            as = fmaf(Wsig[idx * Dd + d], bd[d], as);
        }
        g_bmu2[idx] = am;
        g_bsig2[idx] = as;
    }
}

// ---------------- kernel A: gi[w*32+b][g] = x[b][w][:] . W_ih[g][:] + b_ih[g] ----------------
// M=8192, N=3072, K=4096.  BM=BN=128, BK=16, 256 threads, 8x8 per thread, FFMA2 inner.
__global__ void __launch_bounds__(256) gemm_xw(const float* __restrict__ x,
                                               const float* __restrict__ Wih,
                                               const float* __restrict__ bih)
{
    __shared__ __align__(16) float As[16][132];
    __shared__ __align__(16) float Bs[16][132];
    const int tid = threadIdx.x;
    const int bn = blockIdx.x * 128;
    const int bm = blockIdx.y * 128;
    const int tx = tid & 15, ty = tid >> 4;
    const int lr = tid >> 2, lk = (tid & 3) << 2;

    const float* arow0;
    const float* arow1;
    {
        int m0 = bm + lr;      int w0 = m0 >> 5, b0 = m0 & 31;
        int m1 = bm + lr + 64; int w1 = m1 >> 5, b1 = m1 & 31;
        arow0 = x + (size_t)(b0 * Wt + w0) * IND + lk;
        arow1 = x + (size_t)(b1 * Wt + w1) * IND + lk;
    }
    const float* brow0 = Wih + (size_t)(bn + lr) * IND + lk;
    const float* brow1 = Wih + (size_t)(bn + lr + 64) * IND + lk;

    unsigned long long acc2[8][4];
    #pragma unroll
    for (int i = 0; i < 8; i++)
        #pragma unroll
        for (int j = 0; j < 4; j++) acc2[i][j] = 0ull;

    for (int k0 = 0; k0 < IND; k0 += 16) {
        float4 a0 = *(const float4*)(arow0 + k0);
        float4 a1 = *(const float4*)(arow1 + k0);
        float4 b0 = *(const float4*)(brow0 + k0);
        float4 b1 = *(const float4*)(brow1 + k0);
        __syncthreads();
        As[lk + 0][lr] = a0.x; As[lk + 1][lr] = a0.y; As[lk + 2][lr] = a0.z; As[lk + 3][lr] = a0.w;
        As[lk + 0][lr + 64] = a1.x; As[lk + 1][lr + 64] = a1.y; As[lk + 2][lr + 64] = a1.z; As[lk + 3][lr + 64] = a1.w;
        Bs[lk + 0][lr] = b0.x; Bs[lk + 1][lr] = b0.y; Bs[lk + 2][lr] = b0.z; Bs[lk + 3][lr] = b0.w;
        Bs[lk + 0][lr + 64] = b1.x; Bs[lk + 1][lr + 64] = b1.y; Bs[lk + 2][lr + 64] = b1.z; Bs[lk + 3][lr + 64] = b1.w;
        __syncthreads();
        #pragma unroll
        for (int k = 0; k < 16; k++) {
            float4 av0 = *(const float4*)&As[k][ty * 8];
            float4 av1 = *(const float4*)&As[k][ty * 8 + 4];
            ulonglong2 bv0 = *(const ulonglong2*)&Bs[k][tx * 8];
            ulonglong2 bv1 = *(const ulonglong2*)&Bs[k][tx * 8 + 4];
            float af[8];
            af[0] = av0.x; af[1] = av0.y; af[2] = av0.z; af[3] = av0.w;
            af[4] = av1.x; af[5] = av1.y; af[6] = av1.z; af[7] = av1.w;
            #pragma unroll
            for (int i = 0; i < 8; i++) {
                unsigned long long a2 = pack2(af[i], af[i]);
                fma2(acc2[i][0], a2, bv0.x);
                fma2(acc2[i][1], a2, bv0.y);
                fma2(acc2[i][2], a2, bv1.x);
                fma2(acc2[i][3], a2, bv1.y);
            }
        }
    }

    #pragma unroll
    for (int i = 0; i < 8; i++) {
        int m = bm + ty * 8 + i;
        float* orow = g_gi + (size_t)m * G3 + bn + tx * 8;
        #pragma unroll
        for (int jp = 0; jp < 4; jp += 2) {
            float2 v0 = unpack2(acc2[i][jp]);
            float2 v1 = unpack2(acc2[i][jp + 1]);
            float4 v;
            v.x = v0.x + bih[bn + tx * 8 + jp * 2 + 0];
            v.y = v0.y + bih[bn + tx * 8 + jp * 2 + 1];
            v.z = v1.x + bih[bn + tx * 8 + jp * 2 + 2];
            v.w = v1.y + bih[bn + tx * 8 + jp * 2 + 3];
            *(float4*)(orow + jp * 2) = v;
        }
    }
}

// ---------------- persistent recurrence kernel ----------------
#define SMEM_FLOATS (24 * 1024 + 1124 + 1124 + 128 + 512)
#define SMEM_BYTES  (SMEM_FLOATS * 4)

__global__ void __launch_bounds__(256) recur_kernel(
    const float* __restrict__ Whh, const float* __restrict__ bhh,
    const float* __restrict__ u, const float* __restrict__ Wpnf,
    const float* __restrict__ bpnf, const float* __restrict__ noise,
    float* __restrict__ out)
{
    extern __shared__ float sm[];
    float* s_whh = sm;                       // 24*1024
    float* s_wmd = sm + 24 * 1024;           // 1124
    float* s_wsd = s_wmd + 1124;             // 1124
    float* s_pnf = s_wsd + 1124;             // 128 (100 used)
    float* s_red = s_pnf + 128;              // 8 warps * 2 * 32

    const int bk = blockIdx.x;
    const int tid = threadIdx.x;
    const int lane = tid & 31;
    const int wp = tid >> 5;
    const int i0 = bk * 8;

    for (int idx = tid; idx < 24 * 1024; idx += 256) {
        int r = idx >> 10, k = idx & 1023;
        int ww = r / 3, gate = r % 3;
        s_whh[idx] = Whh[(size_t)(gate * Hd + i0 + ww) * Hd + k];
    }
    if (bk < Zd) {
        for (int j = tid; j < ZH; j += 256) {
            s_wmd[j] = g_Wmd[bk * ZH + j];
            s_wsd[j] = g_Wsd[bk * ZH + j];
        }
        for (int j = tid; j < Zd; j += 256) s_pnf[j] = Wpnf[bk * Zd + j];
    }
    g_h4T[bk * 256 + tid] = 0.f;
    if (bk == 0) for (int j = tid; j < Zd * Bx; j += 256) g_zT[j] = 0.f;

    const int i = i0 + wp;
    const float bhr = bhh[i];
    const float bhz = bhh[Hd + i];
    const float bhn = bhh[2 * Hd + i];
    const float u0 = u[0];
    const float bpq = (bk < Zd) ? bpnf[bk] : 0.f;
    const float bm2 = (bk < Zd) ? g_bmu2[bk] : 0.f;
    const float bs2 = (bk < Zd) ? g_bsig2[bk] : 0.f;

    float* out_z  = out;
    float* out_mu = out + Bx * Wt * Zd;
    float* out_lv = out + 2 * Bx * Wt * Zd;

    const ulonglong2* wr2 = (const ulonglong2*)(s_whh + (wp * 3 + 0) * Hd);
    const ulonglong2* wz2 = (const ulonglong2*)(s_whh + (wp * 3 + 1) * Hd);
    const ulonglong2* wn2 = (const ulonglong2*)(s_whh + (wp * 3 + 2) * Hd);
    const ulonglong2* wm2 = (const ulonglong2*)(s_wmd + Zd);
    const ulonglong2* ws2 = (const ulonglong2*)(s_wsd + Zd);

    // ---- phase 1: gh + gates + h_new (all 128 blocks) ----
    auto phase1 = [&](int t) {
        const float* gip = g_gi + (size_t)(t * Bx + lane) * G3;
        float gir = gip[i], giz = gip[Hd + i], gin = gip[2 * Hd + i];
        const ulonglong2* hb = (const ulonglong2*)(g_h4T + (t & 1) * (Hd * Bx));
        unsigned long long ar_a = 0, ar_b = 0, az_a = 0, az_b = 0, an_a = 0, an_b = 0;
        #pragma unroll 8
        for (int kq = 0; kq < 256; kq++) {
            ulonglong2 h2 = hb[kq * 32 + lane];
            ulonglong2 r2 = wr2[kq];
            ulonglong2 z2 = wz2[kq];
            ulonglong2 n2 = wn2[kq];
            fma2(ar_a, h2.x, r2.x); fma2(ar_b, h2.y, r2.y);
            fma2(az_a, h2.x, z2.x); fma2(az_b, h2.y, z2.y);
            fma2(an_a, h2.x, n2.x); fma2(an_b, h2.y, n2.y);
        }
        float ar = hsum2(ar_a, ar_b);
        float az = hsum2(az_a, az_b);
        float an = hsum2(an_a, an_b);
        float rg = 1.f / (1.f + expf(-(gir + ar + bhr)));
        float zg = 1.f / (1.f + expf(-(giz + az + bhz)));
        float ng = tanhf(gin + rg * (an + bhn));
        int hidx = ((i >> 2) * 32 + lane) * 4 + (i & 3);
        float hold = g_h4T[(t & 1) * (Hd * Bx) + hidx];
        float hnew = (1.f - zg) * ng + zg * hold;
        g_h4T[((t + 1) & 1) * (Hd * Bx) + hidx] = hnew;
    };

    // ---- phase 2: mu / logvar / z_pre (blocks 0..99; block = z-index q) ----
    auto phase2 = [&](int t) {
        if (bk < Zd) {
            float amz = 0.f, asz = 0.f;
            for (int z2 = wp; z2 < Zd; z2 += 8) {
                float zv = g_zT[z2 * 32 + lane];
                amz = fmaf(zv, s_wmd[z2], amz);
                asz = fmaf(zv, s_wsd[z2], asz);
            }
            const ulonglong2* hb2 = (const ulonglong2*)(g_h4T + ((t + 1) & 1) * (Hd * Bx));
            unsigned long long am_a = 0, am_b = 0, as_a = 0, as_b = 0;
            #pragma unroll 8
            for (int kq = wp * 32; kq < wp * 32 + 32; kq++) {
                ulonglong2 h2 = hb2[kq * 32 + lane];
                ulonglong2 m2 = wm2[kq];
                ulonglong2 s2 = ws2[kq];
                fma2(am_a, h2.x, m2.x); fma2(am_b, h2.y, m2.y);
                fma2(as_a, h2.x, s2.x); fma2(as_b, h2.y, s2.y);
            }
            float am = amz + hsum2(am_a, am_b);
            float as = asz + hsum2(as_a, as_b);
            s_red[(wp * 2 + 0) * 32 + lane] = am;
            s_red[(wp * 2 + 1) * 32 + lane] = as;
            __syncthreads();
            if (wp == 0) {
                float m = bm2, s = bs2;
                #pragma unroll
                for (int ww = 0; ww < 8; ww++) {
                    m += s_red[(ww * 2 + 0) * 32 + lane];
                    s += s_red[(ww * 2 + 1) * 32 + lane];
                }
                float lv = fmaxf(s, 0.f) + log1pf(expf(-fabsf(s)));
                float eps = noise[(size_t)(t * Bx + lane) * Zd + bk];
                float zp = m + expf(0.5f * lv) * eps;
                g_zpreT[bk * 32 + lane] = zp;
                out_mu[(size_t)(lane * Wt + t) * Zd + bk] = m;
                out_lv[(size_t)(lane * Wt + t) * Zd + bk] = lv;
            }
        }
    };

    // ---- phase 3: planar flow + outputs (blocks 0..99, warp 0) ----
    auto phase3 = [&](int t) {
        if (bk < Zd && wp == 0) {
            float a0 = 0.f, a1 = 0.f, a2 = 0.f, a3 = 0.f;
            for (int z2 = 0; z2 < Zd; z2 += 4) {
                a0 = fmaf(g_zpreT[(z2 + 0) * 32 + lane], s_pnf[z2 + 0], a0);
                a1 = fmaf(g_zpreT[(z2 + 1) * 32 + lane], s_pnf[z2 + 1], a1);
                a2 = fmaf(g_zpreT[(z2 + 2) * 32 + lane], s_pnf[z2 + 2], a2);
                a3 = fmaf(g_zpreT[(z2 + 3) * 32 + lane], s_pnf[z2 + 3], a3);
            }
            float zp = g_zpreT[bk * 32 + lane];
            float zn = zp + u0 * tanhf(((a0 + a1) + (a2 + a3)) + bpq);
            out_z[(size_t)(lane * Wt + t) * Zd + bk] = zn;
            g_zT[bk * 32 + lane] = zn;
        }
    };

    grid_barrier();          // init (h zero, zT zero) visible everywhere
    phase1(0);
    grid_barrier();

    #pragma unroll 1
    for (int t = 0; t < Wt; t++) {
        phase2(t);
        grid_barrier();
        phase3(t);
        if (t + 1 < Wt) phase1(t + 1);
        grid_barrier();
    }
}

// ---------------- launch ----------------
extern "C" void kernel_launch(void* const* d_in, const int* in_sizes, int n_in,
                              void* d_out, int out_size)
{
    const float* x    = (const float*)d_in[0];
    const float* Wih  = (const float*)d_in[1];
    const float* Whh  = (const float*)d_in[2];
    const float* bih  = (const float*)d_in[3];
    const float* bhh  = (const float*)d_in[4];
    const float* Wd   = (const float*)d_in[5];
    const float* bd   = (const float*)d_in[6];
    const float* Wmu  = (const float*)d_in[7];
    const float* bmu  = (const float*)d_in[8];
    const float* Wsig = (const float*)d_in[9];
    const float* bsig = (const float*)d_in[10];
    const float* u    = (const float*)d_in[11];
    const float* Wpnf = (const float*)d_in[12];
    const float* bpnf = (const float*)d_in[13];
    const float* noise= (const float*)d_in[14];
    float* out = (float*)d_out;

    cudaFuncSetAttribute(recur_kernel, cudaFuncAttributeMaxDynamicSharedMemorySize, SMEM_BYTES);

    prep_kernel<<<(Zd * ZH + 255) / 256, 256>>>(Wd, bd, Wmu, bmu, Wsig, bsig);
    gemm_xw<<<dim3(G3 / 128, (Wt * Bx) / 128), 256>>>(x, Wih, bih);
    recur_kernel<<<NB, 256, SMEM_BYTES>>>(Whh, bhh, u, Wpnf, bpnf, noise, out);
}

// round 3
// speedup vs baseline: 1.6677x; 1.2915x over previous
#include <cuda_runtime.h>
#include <math.h>

#define Bx  32
#define Wt  256
#define IND 4096
#define Hd  1024
#define Zd  100
#define Dd  100
#define G3  3072
#define ZH  1124
#define NHB 128
#define NZB 13
#define HB  (Hd * Bx)          // 32768 floats per h slot
#define NSLOT 8

// ---------------- f32x2 packed-FMA helpers ----------------
__device__ __forceinline__ void fma2(unsigned long long& d, unsigned long long a, unsigned long long b) {
    asm("fma.rn.f32x2 %0, %1, %2, %0;" : "+l"(d) : "l"(a), "l"(b));
}
__device__ __forceinline__ float2 unpack2(unsigned long long v) {
    float2 r;
    asm("mov.b64 {%0, %1}, %2;" : "=f"(r.x), "=f"(r.y) : "l"(v));
    return r;
}
__device__ __forceinline__ unsigned long long pack2(float lo, float hi) {
    unsigned long long r;
    asm("mov.b64 %0, {%1, %2};" : "=l"(r) : "f"(lo), "f"(hi));
    return r;
}
__device__ __forceinline__ float hsum2(unsigned long long a, unsigned long long b) {
    float2 p = unpack2(a), q = unpack2(b);
    return (p.x + p.y) + (q.x + q.y);
}

// ---------------- L2-coherent load/store + sync primitives ----------------
__device__ __forceinline__ ulonglong2 ldcg_u2(const void* p) {
    ulonglong2 v;
    asm volatile("ld.global.cg.v2.u64 {%0,%1},[%2];" : "=l"(v.x), "=l"(v.y) : "l"(p));
    return v;
}
__device__ __forceinline__ float ldcg_f(const float* p) {
    float v; asm volatile("ld.global.cg.f32 %0,[%1];" : "=f"(v) : "l"(p)); return v;
}
__device__ __forceinline__ void stcg_f(float* p, float v) {
    asm volatile("st.global.cg.f32 [%0],%1;" :: "l"(p), "f"(v));
}
__device__ __forceinline__ void arrive(unsigned* c) {
    asm volatile("red.release.gpu.global.add.u32 [%0],%1;" :: "l"(c), "r"(1u) : "memory");
}
__device__ __forceinline__ void wait_ge(const unsigned* c, unsigned target) {
    unsigned v;
    do {
        asm volatile("ld.acquire.gpu.global.u32 %0,[%1];" : "=r"(v) : "l"(c) : "memory");
    } while ((int)(v - target) < 0);
}

// ---------------- device globals ----------------
__device__ __align__(16) float g_gi[25165824];        // [W*B][3H]
__device__ __align__(16) float g_hring[NSLOT * HB];   // 8-deep h ring, quad-packed [kq][b][4]
__device__ __align__(16) float g_zT[Zd * Bx];         // z_t transposed [z][b]
__device__ __align__(16) float g_zpreT[Zd * Bx];      // z before planar flow
__device__ __align__(16) float g_Wmd[Zd * ZH];        // Wmu @ Wd
__device__ __align__(16) float g_Wsd[Zd * ZH];        // Wsig @ Wd
__device__ float g_bmu2[Zd];
__device__ float g_bsig2[Zd];
__device__ unsigned g_hprog;      // 128 per h-step completed
__device__ unsigned g_zaprog;     // 13 per P2 completed
__device__ unsigned g_zbprog;     // 13 per P3 completed

// ---------------- prep: fuse dense into heads + zero state/counters ----------------
__global__ void prep_kernel(const float* __restrict__ Wd, const float* __restrict__ bd,
                            const float* __restrict__ Wmu, const float* __restrict__ bmu,
                            const float* __restrict__ Wsig, const float* __restrict__ bsig)
{
    int idx = blockIdx.x * blockDim.x + threadIdx.x;
    if (idx < Zd * ZH) {
        int q = idx / ZH, j = idx % ZH;
        float am = 0.f, as = 0.f;
        for (int d = 0; d < Dd; d++) {
            float wd = Wd[(size_t)d * ZH + j];
            am = fmaf(Wmu[q * Dd + d], wd, am);
            as = fmaf(Wsig[q * Dd + d], wd, as);
        }
        g_Wmd[idx] = am;
        g_Wsd[idx] = as;
    }
    if (idx < Zd) {
        float am = bmu[idx], as = bsig[idx];
        for (int d = 0; d < Dd; d++) {
            am = fmaf(Wmu[idx * Dd + d], bd[d], am);
            as = fmaf(Wsig[idx * Dd + d], bd[d], as);
        }
        g_bmu2[idx] = am;
        g_bsig2[idx] = as;
    }
    if (idx < HB) g_hring[idx] = 0.f;          // slot 0 = h0 = zeros
    if (idx < Zd * Bx) g_zT[idx] = 0.f;        // z0 = zeros
    if (idx == 0) { g_hprog = 0u; g_zaprog = 0u; g_zbprog = 0u; }
}

// ---------------- kernel A: big input GEMM (unchanged, FFMA2) ----------------
__global__ void __launch_bounds__(256) gemm_xw(const float* __restrict__ x,
                                               const float* __restrict__ Wih,
                                               const float* __restrict__ bih)
{
    __shared__ __align__(16) float As[16][132];
    __shared__ __align__(16) float Bs[16][132];
    const int tid = threadIdx.x;
    const int bn = blockIdx.x * 128;
    const int bm = blockIdx.y * 128;
    const int tx = tid & 15, ty = tid >> 4;
    const int lr = tid >> 2, lk = (tid & 3) << 2;

    const float* arow0;
    const float* arow1;
    {
        int m0 = bm + lr;      int w0 = m0 >> 5, b0 = m0 & 31;
        int m1 = bm + lr + 64; int w1 = m1 >> 5, b1 = m1 & 31;
        arow0 = x + (size_t)(b0 * Wt + w0) * IND + lk;
        arow1 = x + (size_t)(b1 * Wt + w1) * IND + lk;
    }
    const float* brow0 = Wih + (size_t)(bn + lr) * IND + lk;
    const float* brow1 = Wih + (size_t)(bn + lr + 64) * IND + lk;

    unsigned long long acc2[8][4];
    #pragma unroll
    for (int i = 0; i < 8; i++)
        #pragma unroll
        for (int j = 0; j < 4; j++) acc2[i][j] = 0ull;

    for (int k0 = 0; k0 < IND; k0 += 16) {
        float4 a0 = *(const float4*)(arow0 + k0);
        float4 a1 = *(const float4*)(arow1 + k0);
        float4 b0 = *(const float4*)(brow0 + k0);
        float4 b1 = *(const float4*)(brow1 + k0);
        __syncthreads();
        As[lk + 0][lr] = a0.x; As[lk + 1][lr] = a0.y; As[lk + 2][lr] = a0.z; As[lk + 3][lr] = a0.w;
        As[lk + 0][lr + 64] = a1.x; As[lk + 1][lr + 64] = a1.y; As[lk + 2][lr + 64] = a1.z; As[lk + 3][lr + 64] = a1.w;
        Bs[lk + 0][lr] = b0.x; Bs[lk + 1][lr] = b0.y; Bs[lk + 2][lr] = b0.z; Bs[lk + 3][lr] = b0.w;
        Bs[lk + 0][lr + 64] = b1.x; Bs[lk + 1][lr + 64] = b1.y; Bs[lk + 2][lr + 64] = b1.z; Bs[lk + 3][lr + 64] = b1.w;
        __syncthreads();
        #pragma unroll
        for (int k = 0; k < 16; k++) {
            float4 av0 = *(const float4*)&As[k][ty * 8];
            float4 av1 = *(const float4*)&As[k][ty * 8 + 4];
            ulonglong2 bv0 = *(const ulonglong2*)&Bs[k][tx * 8];
            ulonglong2 bv1 = *(const ulonglong2*)&Bs[k][tx * 8 + 4];
            float af[8];
            af[0] = av0.x; af[1] = av0.y; af[2] = av0.z; af[3] = av0.w;
            af[4] = av1.x; af[5] = av1.y; af[6] = av1.z; af[7] = av1.w;
            #pragma unroll
            for (int i = 0; i < 8; i++) {
                unsigned long long a2 = pack2(af[i], af[i]);
                fma2(acc2[i][0], a2, bv0.x);
                fma2(acc2[i][1], a2, bv0.y);
                fma2(acc2[i][2], a2, bv1.x);
                fma2(acc2[i][3], a2, bv1.y);
            }
        }
    }

    #pragma unroll
    for (int i = 0; i < 8; i++) {
        int m = bm + ty * 8 + i;
        float* orow = g_gi + (size_t)m * G3 + bn + tx * 8;
        #pragma unroll
        for (int jp = 0; jp < 4; jp += 2) {
            float2 v0 = unpack2(acc2[i][jp]);
            float2 v1 = unpack2(acc2[i][jp + 1]);
            float4 v;
            v.x = v0.x + bih[bn + tx * 8 + jp * 2 + 0];
            v.y = v0.y + bih[bn + tx * 8 + jp * 2 + 1];
            v.z = v1.x + bih[bn + tx * 8 + jp * 2 + 2];
            v.w = v1.y + bih[bn + tx * 8 + jp * 2 + 3];
            *(float4*)(orow + jp * 2) = v;
        }
    }
}

// ---------------- split-pipeline recurrence: 128 h-CTAs + 13 z-CTAs ----------------
#define SMEM_BYTES (24 * 1024 * 4)     // 96KB (h-CTAs); z-CTAs use ~76KB of it

__global__ void __launch_bounds__(256, 1) recur2(
    const float* __restrict__ Whh, const float* __restrict__ bhh,
    const float* __restrict__ u, const float* __restrict__ Wpnf,
    const float* __restrict__ bpnf, const float* __restrict__ noise,
    float* __restrict__ out)
{
    extern __shared__ float sm[];
    const int bk = blockIdx.x;
    const int tid = threadIdx.x;
    const int lane = tid & 31;
    const int wp = tid >> 5;

    float* out_z  = out;
    float* out_mu = out + Bx * Wt * Zd;
    float* out_lv = out + 2 * Bx * Wt * Zd;
    const float u0 = u[0];

    if (bk < NHB) {
        // ================= h-pipeline CTA =================
        float* s_whh = sm;                       // [8 units][3 gates][1024]
        const int i0 = bk * 8;
        for (int idx = tid; idx < 24 * 1024; idx += 256) {
            int r = idx >> 10, k = idx & 1023;
            int ww = r / 3, gate = r % 3;
            s_whh[idx] = Whh[(size_t)(gate * Hd + i0 + ww) * Hd + k];
        }
        __syncthreads();

        const int i = i0 + wp;
        const float bhr = bhh[i];
        const float bhz = bhh[Hd + i];
        const float bhn = bhh[2 * Hd + i];
        const ulonglong2* wr2 = (const ulonglong2*)(s_whh + (wp * 3 + 0) * Hd);
        const ulonglong2* wz2 = (const ulonglong2*)(s_whh + (wp * 3 + 1) * Hd);
        const ulonglong2* wn2 = (const ulonglong2*)(s_whh + (wp * 3 + 2) * Hd);
        const int hoff = ((i >> 2) * 32 + lane) * 4 + (i & 3);

        #pragma unroll 1
        for (int t = 0; t < Wt; t++) {
            if (tid == 0) {
                if (t > 0) wait_ge(&g_hprog, (unsigned)(NHB * t));          // prev h step done
                if (t >= NSLOT) wait_ge(&g_zaprog, (unsigned)(NZB * (t - 7))); // slot reuse safe
            }
            __syncthreads();

            const float* gip = g_gi + (size_t)(t * Bx + lane) * G3;
            float gir = gip[i], giz = gip[Hd + i], gin = gip[2 * Hd + i];
            const float* hb = g_hring + (size_t)(t & 7) * HB;
            unsigned long long ar0 = 0, ar1 = 0, az0 = 0, az1 = 0, an0 = 0, an1 = 0;
            #pragma unroll 1
            for (int c = 0; c < 256; c += 16) {
                ulonglong2 hv[16];
                #pragma unroll
                for (int j = 0; j < 16; j++)
                    hv[j] = ldcg_u2(hb + ((size_t)(c + j) * 32 + lane) * 4);
                #pragma unroll
                for (int j = 0; j < 16; j++) {
                    ulonglong2 r2 = wr2[c + j];
                    ulonglong2 z2v = wz2[c + j];
                    ulonglong2 n2 = wn2[c + j];
                    fma2(ar0, hv[j].x, r2.x);  fma2(ar1, hv[j].y, r2.y);
                    fma2(az0, hv[j].x, z2v.x); fma2(az1, hv[j].y, z2v.y);
                    fma2(an0, hv[j].x, n2.x);  fma2(an1, hv[j].y, n2.y);
                }
            }
            float ar = hsum2(ar0, ar1);
            float az = hsum2(az0, az1);
            float an = hsum2(an0, an1);
            float rg = 1.f / (1.f + expf(-(gir + ar + bhr)));
            float zg = 1.f / (1.f + expf(-(giz + az + bhz)));
            float ng = tanhf(gin + rg * (an + bhn));
            float hold = ldcg_f(hb + hoff);
            float hnew = (1.f - zg) * ng + zg * hold;
            stcg_f(g_hring + (size_t)((t + 1) & 7) * HB + hoff, hnew);

            __syncthreads();
            if (tid == 0) arrive(&g_hprog);
        }
    } else {
        // ================= z-pipeline CTA =================
        const int zb = bk - NHB;                 // 0..12
        const int q = zb * 8 + wp;               // one z-index per warp
        const bool qa = (q < Zd);
        float* s_wm = sm + wp * 2272;            // [1124 used] mu head (z part then h part)
        float* s_ws = s_wm + 1136;               // sigma head
        float* s_pnf = sm + 8 * 2272 + wp * 104; // planar-flow row for q

        if (qa) {
            for (int j = lane; j < ZH; j += 32) {
                s_wm[j] = g_Wmd[q * ZH + j];
                s_ws[j] = g_Wsd[q * ZH + j];
            }
            for (int j = lane; j < Zd; j += 32) s_pnf[j] = Wpnf[q * Zd + j];
        }
        __syncthreads();

        const float bm2 = qa ? g_bmu2[q] : 0.f;
        const float bs2 = qa ? g_bsig2[q] : 0.f;
        const float bpq = qa ? bpnf[q] : 0.f;
        const ulonglong2* wm2 = (const ulonglong2*)(s_wm + 100);
        const ulonglong2* ws2 = (const ulonglong2*)(s_ws + 100);

        #pragma unroll 1
        for (int t = 0; t < Wt; t++) {
            if (tid == 0) {
                wait_ge(&g_hprog, (unsigned)(NHB * (t + 1)));   // h_new(t) ready
                if (t > 0) wait_ge(&g_zbprog, (unsigned)(NZB * t)); // z(t-1) ready
            }
            __syncthreads();

            float zp = 0.f;
            if (qa) {
                float amz = 0.f, asz = 0.f;
                #pragma unroll 4
                for (int z2 = 0; z2 < Zd; z2++) {
                    float zv = ldcg_f(g_zT + z2 * 32 + lane);
                    amz = fmaf(zv, s_wm[z2], amz);
                    asz = fmaf(zv, s_ws[z2], asz);
                }
                const float* hb = g_hring + (size_t)((t + 1) & 7) * HB;
                unsigned long long am0 = 0, am1 = 0, as0 = 0, as1 = 0;
                #pragma unroll 1
                for (int c = 0; c < 256; c += 16) {
                    ulonglong2 hv[16];
                    #pragma unroll
                    for (int j = 0; j < 16; j++)
                        hv[j] = ldcg_u2(hb + ((size_t)(c + j) * 32 + lane) * 4);
                    #pragma unroll
                    for (int j = 0; j < 16; j++) {
                        ulonglong2 m2 = wm2[c + j];
                        ulonglong2 s2 = ws2[c + j];
                        fma2(am0, hv[j].x, m2.x); fma2(am1, hv[j].y, m2.y);
                        fma2(as0, hv[j].x, s2.x); fma2(as1, hv[j].y, s2.y);
                    }
                }
                float m = bm2 + amz + hsum2(am0, am1);
                float s = bs2 + asz + hsum2(as0, as1);
                float lv = fmaxf(s, 0.f) + log1pf(expf(-fabsf(s)));
                float eps = noise[(size_t)(t * Bx + lane) * Zd + q];
                zp = m + expf(0.5f * lv) * eps;
                stcg_f(g_zpreT + q * 32 + lane, zp);
                out_mu[(size_t)(lane * Wt + t) * Zd + q] = m;
                out_lv[(size_t)(lane * Wt + t) * Zd + q] = lv;
            }
            __syncthreads();
            if (tid == 0) {
                arrive(&g_zaprog);
                wait_ge(&g_zaprog, (unsigned)(NZB * (t + 1)));  // all zpre ready
            }
            __syncthreads();

            if (qa) {
                float a0 = 0.f, a1 = 0.f;
                #pragma unroll 4
                for (int z2 = 0; z2 < Zd; z2 += 2) {
                    a0 = fmaf(ldcg_f(g_zpreT + (z2 + 0) * 32 + lane), s_pnf[z2 + 0], a0);
                    a1 = fmaf(ldcg_f(g_zpreT + (z2 + 1) * 32 + lane), s_pnf[z2 + 1], a1);
                }
                float zn = zp + u0 * tanhf((a0 + a1) + bpq);
                out_z[(size_t)(lane * Wt + t) * Zd + q] = zn;
                stcg_f(g_zT + q * 32 + lane, zn);
            }
            __syncthreads();
            if (tid == 0) arrive(&g_zbprog);
        }
    }
}

// ---------------- launch ----------------
extern "C" void kernel_launch(void* const* d_in, const int* in_sizes, int n_in,
                              void* d_out, int out_size)
{
    const float* x    = (const float*)d_in[0];
    const float* Wih  = (const float*)d_in[1];
    const float* Whh  = (const float*)d_in[2];
    const float* bih  = (const float*)d_in[3];
    const float* bhh  = (const float*)d_in[4];
    const float* Wd   = (const float*)d_in[5];
    const float* bd   = (const float*)d_in[6];
    const float* Wmu  = (const float*)d_in[7];
    const float* bmu  = (const float*)d_in[8];
    const float* Wsig = (const float*)d_in[9];
    const float* bsig = (const float*)d_in[10];
    const float* u    = (const float*)d_in[11];
    const float* Wpnf = (const float*)d_in[12];
    const float* bpnf = (const float*)d_in[13];
    const float* noise= (const float*)d_in[14];
    float* out = (float*)d_out;

    cudaFuncSetAttribute(recur2, cudaFuncAttributeMaxDynamicSharedMemorySize, SMEM_BYTES);

    prep_kernel<<<(Zd * ZH + 255) / 256, 256>>>(Wd, bd, Wmu, bmu, Wsig, bsig);
    gemm_xw<<<dim3(G3 / 128, (Wt * Bx) / 128), 256>>>(x, Wih, bih);
    recur2<<<NHB + NZB, 256, SMEM_BYTES>>>(Whh, bhh, u, Wpnf, bpnf, noise, out);
}

// round 4
// speedup vs baseline: 1.6848x; 1.0103x over previous
#include <cuda_runtime.h>
#include <math.h>

#define Bx  32
#define Wt  256
#define IND 4096
#define Hd  1024
#define Zd  100
#define Dd  100
#define G3  3072
#define ZH  1124
#define NHB 128
#define NZB 13
#define HB  (Hd * Bx)          // 32768 floats per h slot
#define NSLOT 8

// ---------------- f32x2 packed-FMA helpers ----------------
__device__ __forceinline__ void fma2(unsigned long long& d, unsigned long long a, unsigned long long b) {
    asm("fma.rn.f32x2 %0, %1, %2, %0;" : "+l"(d) : "l"(a), "l"(b));
}
__device__ __forceinline__ float2 unpack2(unsigned long long v) {
    float2 r;
    asm("mov.b64 {%0, %1}, %2;" : "=f"(r.x), "=f"(r.y) : "l"(v));
    return r;
}
__device__ __forceinline__ unsigned long long pack2(float lo, float hi) {
    unsigned long long r;
    asm("mov.b64 %0, {%1, %2};" : "=l"(r) : "f"(lo), "f"(hi));
    return r;
}
__device__ __forceinline__ float hsum2(unsigned long long a, unsigned long long b) {
    float2 p = unpack2(a), q = unpack2(b);
    return (p.x + p.y) + (q.x + q.y);
}

// ---------------- L2-coherent load/store + sync primitives ----------------
__device__ __forceinline__ ulonglong2 ldcg_u2(const void* p) {
    ulonglong2 v;
    asm volatile("ld.global.cg.v2.u64 {%0,%1},[%2];" : "=l"(v.x), "=l"(v.y) : "l"(p));
    return v;
}
__device__ __forceinline__ float ldcg_f(const float* p) {
    float v; asm volatile("ld.global.cg.f32 %0,[%1];" : "=f"(v) : "l"(p)); return v;
}
__device__ __forceinline__ void stcg_f(float* p, float v) {
    asm volatile("st.global.cg.f32 [%0],%1;" :: "l"(p), "f"(v));
}
__device__ __forceinline__ void arrive(unsigned* c) {
    asm volatile("red.release.gpu.global.add.u32 [%0],%1;" :: "l"(c), "r"(1u) : "memory");
}
__device__ __forceinline__ void wait_ge(const unsigned* c, unsigned target) {
    unsigned v;
    asm volatile("ld.acquire.gpu.global.u32 %0,[%1];" : "=r"(v) : "l"(c) : "memory");
    while ((int)(v - target) < 0) {
        __nanosleep(32);
        asm volatile("ld.acquire.gpu.global.u32 %0,[%1];" : "=r"(v) : "l"(c) : "memory");
    }
}

// ---------------- device globals ----------------
__device__ __align__(16) float g_gi[25165824];        // [W][3H][B]  (transposed!)
__device__ __align__(16) float g_hring[NSLOT * HB];   // 8-deep h ring, quad-packed [kq][b][4]
__device__ __align__(16) float g_zT[Zd * Bx];         // z_t transposed [z][b]
__device__ __align__(16) float g_zpreT[Zd * Bx];      // z before planar flow
__device__ __align__(16) float g_Wmd[Zd * ZH];        // Wmu @ Wd
__device__ __align__(16) float g_Wsd[Zd * ZH];        // Wsig @ Wd
__device__ float g_bmu2[Zd];
__device__ float g_bsig2[Zd];
__device__ unsigned g_hprog;      // 128 per h-step completed
__device__ unsigned g_zaprog;     // 13 per P2 completed
__device__ unsigned g_zbprog;     // 13 per P3 completed

// ---------------- prep: fuse dense into heads + zero state/counters ----------------
__global__ void prep_kernel(const float* __restrict__ Wd, const float* __restrict__ bd,
                            const float* __restrict__ Wmu, const float* __restrict__ bmu,
                            const float* __restrict__ Wsig, const float* __restrict__ bsig)
{
    int idx = blockIdx.x * blockDim.x + threadIdx.x;
    if (idx < Zd * ZH) {
        int q = idx / ZH, j = idx % ZH;
        float am = 0.f, as = 0.f;
        for (int d = 0; d < Dd; d++) {
            float wd = Wd[(size_t)d * ZH + j];
            am = fmaf(Wmu[q * Dd + d], wd, am);
            as = fmaf(Wsig[q * Dd + d], wd, as);
        }
        g_Wmd[idx] = am;
        g_Wsd[idx] = as;
    }
    if (idx < Zd) {
        float am = bmu[idx], as = bsig[idx];
        for (int d = 0; d < Dd; d++) {
            am = fmaf(Wmu[idx * Dd + d], bd[d], am);
            as = fmaf(Wsig[idx * Dd + d], bd[d], as);
        }
        g_bmu2[idx] = am;
        g_bsig2[idx] = as;
    }
    if (idx < HB) g_hring[idx] = 0.f;          // slot 0 = h0 = zeros
    if (idx < Zd * Bx) g_zT[idx] = 0.f;        // z0 = zeros
    if (idx == 0) { g_hprog = 0u; g_zaprog = 0u; g_zbprog = 0u; }
}

// ---------------- kernel A: big input GEMM (FFMA2), output transposed [w][n][b] ----------------
__global__ void __launch_bounds__(256) gemm_xw(const float* __restrict__ x,
                                               const float* __restrict__ Wih,
                                               const float* __restrict__ bih)
{
    __shared__ __align__(16) float As[16][132];
    __shared__ __align__(16) float Bs[16][132];
    const int tid = threadIdx.x;
    const int bn = blockIdx.x * 128;
    const int bm = blockIdx.y * 128;
    const int tx = tid & 15, ty = tid >> 4;
    const int lr = tid >> 2, lk = (tid & 3) << 2;

    const float* arow0;
    const float* arow1;
    {
        int m0 = bm + lr;      int w0 = m0 >> 5, b0 = m0 & 31;
        int m1 = bm + lr + 64; int w1 = m1 >> 5, b1 = m1 & 31;
        arow0 = x + (size_t)(b0 * Wt + w0) * IND + lk;
        arow1 = x + (size_t)(b1 * Wt + w1) * IND + lk;
    }
    const float* brow0 = Wih + (size_t)(bn + lr) * IND + lk;
    const float* brow1 = Wih + (size_t)(bn + lr + 64) * IND + lk;

    unsigned long long acc2[8][4];
    #pragma unroll
    for (int i = 0; i < 8; i++)
        #pragma unroll
        for (int j = 0; j < 4; j++) acc2[i][j] = 0ull;

    for (int k0 = 0; k0 < IND; k0 += 16) {
        float4 a0 = *(const float4*)(arow0 + k0);
        float4 a1 = *(const float4*)(arow1 + k0);
        float4 b0 = *(const float4*)(brow0 + k0);
        float4 b1 = *(const float4*)(brow1 + k0);
        __syncthreads();
        As[lk + 0][lr] = a0.x; As[lk + 1][lr] = a0.y; As[lk + 2][lr] = a0.z; As[lk + 3][lr] = a0.w;
        As[lk + 0][lr + 64] = a1.x; As[lk + 1][lr + 64] = a1.y; As[lk + 2][lr + 64] = a1.z; As[lk + 3][lr + 64] = a1.w;
        Bs[lk + 0][lr] = b0.x; Bs[lk + 1][lr] = b0.y; Bs[lk + 2][lr] = b0.z; Bs[lk + 3][lr] = b0.w;
        Bs[lk + 0][lr + 64] = b1.x; Bs[lk + 1][lr + 64] = b1.y; Bs[lk + 2][lr + 64] = b1.z; Bs[lk + 3][lr + 64] = b1.w;
        __syncthreads();
        #pragma unroll
        for (int k = 0; k < 16; k++) {
            float4 av0 = *(const float4*)&As[k][ty * 8];
            float4 av1 = *(const float4*)&As[k][ty * 8 + 4];
            ulonglong2 bv0 = *(const ulonglong2*)&Bs[k][tx * 8];
            ulonglong2 bv1 = *(const ulonglong2*)&Bs[k][tx * 8 + 4];
            float af[8];
            af[0] = av0.x; af[1] = av0.y; af[2] = av0.z; af[3] = av0.w;
            af[4] = av1.x; af[5] = av1.y; af[6] = av1.z; af[7] = av1.w;
            #pragma unroll
            for (int i = 0; i < 8; i++) {
                unsigned long long a2 = pack2(af[i], af[i]);
                fma2(acc2[i][0], a2, bv0.x);
                fma2(acc2[i][1], a2, bv0.y);
                fma2(acc2[i][2], a2, bv1.x);
                fma2(acc2[i][3], a2, bv1.y);
            }
        }
    }

    // Epilogue: m = bm + ty*8 + i encodes (w = m>>5, b = m&31); i spans 8 consecutive b (same w).
    const int w0 = (bm + ty * 8) >> 5;
    const int b0 = (bm + ty * 8) & 31;
    #pragma unroll
    for (int jp = 0; jp < 4; jp++) {
        float2 p[8];
        #pragma unroll
        for (int i = 0; i < 8; i++) p[i] = unpack2(acc2[i][jp]);
        #pragma unroll
        for (int half = 0; half < 2; half++) {
            int n = bn + tx * 8 + jp * 2 + half;
            float bias = bih[n];
            float4 v0, v1;
            v0.x = (half ? p[0].y : p[0].x) + bias;
            v0.y = (half ? p[1].y : p[1].x) + bias;
            v0.z = (half ? p[2].y : p[2].x) + bias;
            v0.w = (half ? p[3].y : p[3].x) + bias;
            v1.x = (half ? p[4].y : p[4].x) + bias;
            v1.y = (half ? p[5].y : p[5].x) + bias;
            v1.z = (half ? p[6].y : p[6].x) + bias;
            v1.w = (half ? p[7].y : p[7].x) + bias;
            float* base = g_gi + ((size_t)w0 * G3 + n) * 32 + b0;
            *(float4*)base = v0;
            *(float4*)(base + 4) = v1;
        }
    }
}

// ---------------- split-pipeline recurrence: 128 h-CTAs (k-split) + 13 z-CTAs ----------------
#define SMEM_BYTES ((24 * 1024 + 6 * 1024) * 4)    // 96KB weights + 24KB reduction = 120KB

__global__ void __launch_bounds__(256, 1) recur2(
    const float* __restrict__ Whh, const float* __restrict__ bhh,
    const float* __restrict__ u, const float* __restrict__ Wpnf,
    const float* __restrict__ bpnf, const float* __restrict__ noise,
    float* __restrict__ out)
{
    extern __shared__ float sm[];
    const int bk = blockIdx.x;
    const int tid = threadIdx.x;
    const int lane = tid & 31;
    const int wp = tid >> 5;

    float* out_z  = out;
    float* out_mu = out + Bx * Wt * Zd;
    float* out_lv = out + 2 * Bx * Wt * Zd;
    const float u0 = u[0];

    if (bk < NHB) {
        // ================= h-pipeline CTA (k-split across warps) =================
        float* s_whh = sm;                  // [256 kq][8 u][3 g][4] = 24576 floats
        float* s_red = sm + 24 * 1024;      // [8 ww][24 ug][32 lane]
        const int i0 = bk * 8;

        for (int idx = tid; idx < 24576; idx += 256) {
            int c = idx & 3;
            int rest = idx >> 2;
            int g = rest % 3;
            int t2 = rest / 3;
            int uu = t2 & 7;
            int kq = t2 >> 3;
            s_whh[idx] = Whh[(size_t)(g * Hd + i0 + uu) * Hd + kq * 4 + c];
        }
        __syncthreads();

        const int i = i0 + wp;                         // unit this warp finalizes
        const float bhr = bhh[i];
        const float bhz = bhh[Hd + i];
        const float bhn = bhh[2 * Hd + i];
        const int hoff = ((i >> 2) * 32 + lane) * 4 + (i & 3);
        const int kq0 = wp * 32;                       // k-slice this warp accumulates

        #pragma unroll 1
        for (int t = 0; t < Wt; t++) {
            if (tid == 0) {
                if (t > 0) wait_ge(&g_hprog, (unsigned)(NHB * t));
                if (t >= NSLOT) wait_ge(&g_zaprog, (unsigned)(NZB * (t - (NSLOT - 1))));
            }
            __syncthreads();

            // early loads (independent of the dot products)
            const float* gib = g_gi + ((size_t)t * G3) * 32;
            float gir = gib[(size_t)(0 * Hd + i) * 32 + lane];
            float giz = gib[(size_t)(1 * Hd + i) * 32 + lane];
            float gin = gib[(size_t)(2 * Hd + i) * 32 + lane];
            const float* hb = g_hring + (size_t)(t & 7) * HB;
            float hold = ldcg_f(hb + hoff);

            // k-slice partial sums: 24 (unit,gate) packed accumulators
            unsigned long long acc[24];
            #pragma unroll
            for (int ug = 0; ug < 24; ug++) acc[ug] = 0ull;

            #pragma unroll 1
            for (int jb = 0; jb < 32; jb += 8) {
                ulonglong2 hv[8];
                #pragma unroll
                for (int j = 0; j < 8; j++)
                    hv[j] = ldcg_u2(hb + (size_t)((kq0 + jb + j) * 32 + lane) * 4);
                #pragma unroll
                for (int j = 0; j < 8; j++) {
                    const ulonglong2* wq = (const ulonglong2*)(s_whh + (size_t)(kq0 + jb + j) * 96);
                    #pragma unroll
                    for (int ug = 0; ug < 24; ug++) {
                        ulonglong2 w2 = wq[ug];
                        fma2(acc[ug], hv[j].x, w2.x);
                        fma2(acc[ug], hv[j].y, w2.y);
                    }
                }
            }
            #pragma unroll
            for (int ug = 0; ug < 24; ug++) {
                float2 p = unpack2(acc[ug]);
                s_red[(wp * 24 + ug) * 32 + lane] = p.x + p.y;
            }
            __syncthreads();

            // cross-warp reduce: warp wp finalizes unit i = i0+wp
            float ar = 0.f, az = 0.f, an = 0.f;
            #pragma unroll
            for (int ww = 0; ww < 8; ww++) {
                ar += s_red[(ww * 24 + wp * 3 + 0) * 32 + lane];
                az += s_red[(ww * 24 + wp * 3 + 1) * 32 + lane];
                an += s_red[(ww * 24 + wp * 3 + 2) * 32 + lane];
            }
            float rg = 1.f / (1.f + expf(-(gir + ar + bhr)));
            float zg = 1.f / (1.f + expf(-(giz + az + bhz)));
            float ng = tanhf(gin + rg * (an + bhn));
            float hnew = (1.f - zg) * ng + zg * hold;
            stcg_f(g_hring + (size_t)((t + 1) & 7) * HB + hoff, hnew);

            __syncthreads();
            if (tid == 0) arrive(&g_hprog);
        }
    } else {
        // ================= z-pipeline CTA =================
        const int zb = bk - NHB;                 // 0..12
        const int q = zb * 8 + wp;               // one z-index per warp
        const bool qa = (q < Zd);
        float* s_wm = sm + wp * 2272;            // mu head (z part then h part)
        float* s_ws = s_wm + 1136;               // sigma head
        float* s_pnf = sm + 8 * 2272 + wp * 104; // planar-flow row for q

        if (qa) {
            for (int j = lane; j < ZH; j += 32) {
                s_wm[j] = g_Wmd[q * ZH + j];
                s_ws[j] = g_Wsd[q * ZH + j];
            }
            for (int j = lane; j < Zd; j += 32) s_pnf[j] = Wpnf[q * Zd + j];
        }
        __syncthreads();

        const float bm2 = qa ? g_bmu2[q] : 0.f;
        const float bs2 = qa ? g_bsig2[q] : 0.f;
        const float bpq = qa ? bpnf[q] : 0.f;
        const ulonglong2* wm2 = (const ulonglong2*)(s_wm + 100);
        const ulonglong2* ws2 = (const ulonglong2*)(s_ws + 100);

        #pragma unroll 1
        for (int t = 0; t < Wt; t++) {
            if (tid == 0) {
                wait_ge(&g_hprog, (unsigned)(NHB * (t + 1)));   // h_new(t) ready
                if (t > 0) wait_ge(&g_zbprog, (unsigned)(NZB * t)); // z(t-1) ready
            }
            __syncthreads();

            float zp = 0.f;
            if (qa) {
                float amz = 0.f, asz = 0.f;
                #pragma unroll 4
                for (int z2 = 0; z2 < Zd; z2++) {
                    float zv = ldcg_f(g_zT + z2 * 32 + lane);
                    amz = fmaf(zv, s_wm[z2], amz);
                    asz = fmaf(zv, s_ws[z2], asz);
                }
                const float* hb = g_hring + (size_t)((t + 1) & 7) * HB;
                unsigned long long am0 = 0, am1 = 0, as0 = 0, as1 = 0;
                #pragma unroll 1
                for (int c = 0; c < 256; c += 16) {
                    ulonglong2 hv[16];
                    #pragma unroll
                    for (int j = 0; j < 16; j++)
                        hv[j] = ldcg_u2(hb + (size_t)((c + j) * 32 + lane) * 4);
                    #pragma unroll
                    for (int j = 0; j < 16; j++) {
                        ulonglong2 m2 = wm2[c + j];
                        ulonglong2 s2 = ws2[c + j];
                        fma2(am0, hv[j].x, m2.x); fma2(am1, hv[j].y, m2.y);
                        fma2(as0, hv[j].x, s2.x); fma2(as1, hv[j].y, s2.y);
                    }
                }
                float m = bm2 + amz + hsum2(am0, am1);
                float s = bs2 + asz + hsum2(as0, as1);
                float lv = fmaxf(s, 0.f) + log1pf(expf(-fabsf(s)));
                float eps = noise[(size_t)(t * Bx + lane) * Zd + q];
                zp = m + expf(0.5f * lv) * eps;
                stcg_f(g_zpreT + q * 32 + lane, zp);
                out_mu[(size_t)(lane * Wt + t) * Zd + q] = m;
                out_lv[(size_t)(lane * Wt + t) * Zd + q] = lv;
            }
            __syncthreads();
            if (tid == 0) {
                arrive(&g_zaprog);
                wait_ge(&g_zaprog, (unsigned)(NZB * (t + 1)));  // all zpre ready
            }
            __syncthreads();

            if (qa) {
                float a0 = 0.f, a1 = 0.f;
                #pragma unroll 4
                for (int z2 = 0; z2 < Zd; z2 += 2) {
                    a0 = fmaf(ldcg_f(g_zpreT + (z2 + 0) * 32 + lane), s_pnf[z2 + 0], a0);
                    a1 = fmaf(ldcg_f(g_zpreT + (z2 + 1) * 32 + lane), s_pnf[z2 + 1], a1);
                }
                float zn = zp + u0 * tanhf((a0 + a1) + bpq);
                out_z[(size_t)(lane * Wt + t) * Zd + q] = zn;
                stcg_f(g_zT + q * 32 + lane, zn);
            }
            __syncthreads();
            if (tid == 0) arrive(&g_zbprog);
        }
    }
}

// ---------------- launch ----------------
extern "C" void kernel_launch(void* const* d_in, const int* in_sizes, int n_in,
                              void* d_out, int out_size)
{
    const float* x    = (const float*)d_in[0];
    const float* Wih  = (const float*)d_in[1];
    const float* Whh  = (const float*)d_in[2];
    const float* bih  = (const float*)d_in[3];
    const float* bhh  = (const float*)d_in[4];
    const float* Wd   = (const float*)d_in[5];
    const float* bd   = (const float*)d_in[6];
    const float* Wmu  = (const float*)d_in[7];
    const float* bmu  = (const float*)d_in[8];
    const float* Wsig = (const float*)d_in[9];
    const float* bsig = (const float*)d_in[10];
    const float* u    = (const float*)d_in[11];
    const float* Wpnf = (const float*)d_in[12];
    const float* bpnf = (const float*)d_in[13];
    const float* noise= (const float*)d_in[14];
    float* out = (float*)d_out;

    cudaFuncSetAttribute(recur2, cudaFuncAttributeMaxDynamicSharedMemorySize, SMEM_BYTES);

    prep_kernel<<<(Zd * ZH + 255) / 256, 256>>>(Wd, bd, Wmu, bmu, Wsig, bsig);
    gemm_xw<<<dim3(G3 / 128, (Wt * Bx) / 128), 256>>>(x, Wih, bih);
    recur2<<<NHB + NZB, 256, SMEM_BYTES>>>(Whh, bhh, u, Wpnf, bpnf, noise, out);
}

// round 7
// speedup vs baseline: 2.3380x; 1.3877x over previous
#include <cuda_runtime.h>
#include <cuda_bf16.h>
#include <math.h>
#include <stdint.h>

#define Bx  32
#define Wt  256
#define IND 4096
#define Hd  1024
#define Zd  100
#define Dd  100
#define G3  3072
#define ZH  1124
#define NHB 128
#define NZB 13
#define HB  (Hd * Bx)
#define NSLOT 8

// ---------------- f32x2 packed-FMA helpers (recurrence) ----------------
__device__ __forceinline__ void fma2(unsigned long long& d, unsigned long long a, unsigned long long b) {
    asm("fma.rn.f32x2 %0, %1, %2, %0;" : "+l"(d) : "l"(a), "l"(b));
}
__device__ __forceinline__ float2 unpack2(unsigned long long v) {
    float2 r;
    asm("mov.b64 {%0, %1}, %2;" : "=f"(r.x), "=f"(r.y) : "l"(v));
    return r;
}
__device__ __forceinline__ float hsum2(unsigned long long a, unsigned long long b) {
    float2 p = unpack2(a), q = unpack2(b);
    return (p.x + p.y) + (q.x + q.y);
}

// ---------------- L2-coherent load/store + sync primitives ----------------
__device__ __forceinline__ ulonglong2 ldcg_u2(const void* p) {
    ulonglong2 v;
    asm volatile("ld.global.cg.v2.u64 {%0,%1},[%2];" : "=l"(v.x), "=l"(v.y) : "l"(p));
    return v;
}
__device__ __forceinline__ float ldcg_f(const float* p) {
    float v; asm volatile("ld.global.cg.f32 %0,[%1];" : "=f"(v) : "l"(p)); return v;
}
__device__ __forceinline__ void stcg_f(float* p, float v) {
    asm volatile("st.global.cg.f32 [%0],%1;" :: "l"(p), "f"(v));
}
__device__ __forceinline__ void arrive(unsigned* c) {
    asm volatile("red.release.gpu.global.add.u32 [%0],%1;" :: "l"(c), "r"(1u) : "memory");
}
__device__ __forceinline__ void wait_ge(const unsigned* c, unsigned target) {
    unsigned v;
    asm volatile("ld.acquire.gpu.global.u32 %0,[%1];" : "=r"(v) : "l"(c) : "memory");
    while ((int)(v - target) < 0) {
        __nanosleep(32);
        asm volatile("ld.acquire.gpu.global.u32 %0,[%1];" : "=r"(v) : "l"(c) : "memory");
    }
}

// ---------------- mma.sync helpers (sm_80+ ISA; works on plain sm_103 target) ----------------
__device__ __forceinline__ uint32_t smem_u32(const void* p) {
    uint32_t a;
    asm("{ .reg .u64 t; cvta.to.shared.u64 t, %1; cvt.u32.u64 %0, t; }" : "=r"(a) : "l"(p));
    return a;
}
__device__ __forceinline__ void ldsm4(uint32_t* r, uint32_t addr) {
    asm volatile("ldmatrix.sync.aligned.m8n8.x4.shared.b16 {%0,%1,%2,%3},[%4];"
                 : "=r"(r[0]), "=r"(r[1]), "=r"(r[2]), "=r"(r[3]) : "r"(addr));
}
__device__ __forceinline__ void mma16816(float* c, const uint32_t* a, const uint32_t* b) {
    asm volatile("mma.sync.aligned.m16n8k16.row.col.f32.bf16.bf16.f32 "
                 "{%0,%1,%2,%3},{%4,%5,%6,%7},{%8,%9},{%0,%1,%2,%3};"
                 : "+f"(c[0]), "+f"(c[1]), "+f"(c[2]), "+f"(c[3])
                 : "r"(a[0]), "r"(a[1]), "r"(a[2]), "r"(a[3]), "r"(b[0]), "r"(b[1]));
}
__device__ __forceinline__ void cp_async16(uint32_t saddr, const void* gaddr) {
    asm volatile("cp.async.cg.shared.global [%0],[%1],16;" :: "r"(saddr), "l"(gaddr));
}
#define CP_COMMIT() asm volatile("cp.async.commit_group;" ::: "memory")
#define CP_WAIT(n)  asm volatile("cp.async.wait_group %0;" :: "n"(n) : "memory")

// ---------------- device globals ----------------
__device__ __align__(16) float g_gi[25165824];        // [W][3H][B]
__device__ __align__(16) __nv_bfloat16 g_xh[8192 * 4096];
__device__ __align__(16) __nv_bfloat16 g_xl[8192 * 4096];
__device__ __align__(16) __nv_bfloat16 g_wh[3072 * 4096];
__device__ __align__(16) __nv_bfloat16 g_wl[3072 * 4096];
__device__ __align__(16) float g_hring[NSLOT * HB];
__device__ __align__(16) float g_zT[Zd * Bx];
__device__ __align__(16) float g_zpreT[Zd * Bx];
__device__ __align__(16) float g_Wmd[Zd * ZH];
__device__ __align__(16) float g_Wsd[Zd * ZH];
__device__ float g_bmu2[Zd];
__device__ float g_bsig2[Zd];
__device__ unsigned g_hprog;
__device__ unsigned g_zaprog;
__device__ unsigned g_zbprog;

// ---------------- prep ----------------
__global__ void prep_kernel(const float* __restrict__ Wd, const float* __restrict__ bd,
                            const float* __restrict__ Wmu, const float* __restrict__ bmu,
                            const float* __restrict__ Wsig, const float* __restrict__ bsig)
{
    int idx = blockIdx.x * blockDim.x + threadIdx.x;
    if (idx < Zd * ZH) {
        int q = idx / ZH, j = idx % ZH;
        float am = 0.f, as = 0.f;
        for (int d = 0; d < Dd; d++) {
            float wd = Wd[(size_t)d * ZH + j];
            am = fmaf(Wmu[q * Dd + d], wd, am);
            as = fmaf(Wsig[q * Dd + d], wd, as);
        }
        g_Wmd[idx] = am;
        g_Wsd[idx] = as;
    }
    if (idx < Zd) {
        float am = bmu[idx], as = bsig[idx];
        for (int d = 0; d < Dd; d++) {
            am = fmaf(Wmu[idx * Dd + d], bd[d], am);
            as = fmaf(Wsig[idx * Dd + d], bd[d], as);
        }
        g_bmu2[idx] = am;
        g_bsig2[idx] = as;
    }
    if (idx < HB) g_hring[idx] = 0.f;
    if (idx < Zd * Bx) g_zT[idx] = 0.f;
    if (idx == 0) { g_hprog = 0u; g_zaprog = 0u; g_zbprog = 0u; }
}

// ---------------- split conversions ----------------
__device__ __forceinline__ void split8(const float* s, __nv_bfloat16* h, __nv_bfloat16* l) {
    #pragma unroll
    for (int i = 0; i < 8; i++) {
        float v = s[i];
        __nv_bfloat16 hb = __float2bfloat16_rn(v);
        h[i] = hb;
        l[i] = __float2bfloat16_rn(v - __bfloat162float(hb));
    }
}

__global__ void __launch_bounds__(256) conv_x(const float* __restrict__ x) {
    size_t idx = ((size_t)blockIdx.x * 256 + threadIdx.x) * 8;
    int m = (int)(idx >> 12), k = (int)(idx & 4095);
    int b = m & 31, w = m >> 5;
    float s[8];
    *(float4*)(s)     = *(const float4*)(x + ((size_t)(b * Wt + w) << 12) + k);
    *(float4*)(s + 4) = *(const float4*)(x + ((size_t)(b * Wt + w) << 12) + k + 4);
    __nv_bfloat16 h[8], l[8];
    split8(s, h, l);
    *(uint4*)(g_xh + idx) = *(uint4*)h;
    *(uint4*)(g_xl + idx) = *(uint4*)l;
}

__global__ void __launch_bounds__(256) conv_w(const float* __restrict__ Wih) {
    size_t idx = ((size_t)blockIdx.x * 256 + threadIdx.x) * 8;
    float s[8];
    *(float4*)(s)     = *(const float4*)(Wih + idx);
    *(float4*)(s + 4) = *(const float4*)(Wih + idx + 4);
    __nv_bfloat16 h[8], l[8];
    split8(s, h, l);
    *(uint4*)(g_wh + idx) = *(uint4*)h;
    *(uint4*)(g_wl + idx) = *(uint4*)l;
}

// ---------------- mma.sync GEMM: gi = (xh+xl).(wh+wl)^T via 3 bf16 passes ----------------
// CTA 128x128, BK=32, 2-stage cp.async double buffer, 8 warps (warp tile 32x64).
// K-iterations: 3 passes * 128 chunks = 384.
#define STG_BYTES 16384          // A 8KB + B 8KB per stage
#define SMB_B 8192

__global__ void __launch_bounds__(256) gemm_mma(const float* __restrict__ bih) {
    __shared__ __align__(128) char smg[2 * STG_BYTES];
    const uint32_t sbase = smem_u32(smg);
    const int tid = threadIdx.x;
    const int lane = tid & 31;
    const int wid = tid >> 5;
    const int tn = blockIdx.x;        // 0..23
    const int tm = blockIdx.y;        // 0..63
    const int wm = (wid & 3) * 32;    // warp M offset in tile
    const int wn = (wid >> 2) * 64;   // warp N offset in tile

    // swizzled byte offset inside a 128x32-bf16 tile (64B rows)
    auto sw = [](int r, int cb) -> uint32_t {
        return (uint32_t)(r * 64 + ((cb ^ ((r >> 1) & 3)) << 4));
    };

    // ---- per-lane ldmatrix addresses (offsets within stage) ----
    uint32_t aoff[2][2], boff[4][2];
    {
        int ml = wm + (lane & 15);
        #pragma unroll
        for (int mt = 0; mt < 2; mt++)
            #pragma unroll
            for (int kh = 0; kh < 2; kh++)
                aoff[mt][kh] = sw(ml + mt * 16, kh * 2 + (lane >> 4));
        int nl = wn + ((lane >> 4) << 3) + (lane & 7);
        #pragma unroll
        for (int p = 0; p < 4; p++)
            #pragma unroll
            for (int kh = 0; kh < 2; kh++)
                boff[p][kh] = (uint32_t)SMB_B + sw(nl + p * 16, kh * 2 + ((lane >> 3) & 1));
    }

    // ---- loader ----
    auto load_chunk = [&](int chunk, int stage) {
        int pass = chunk >> 7;
        int k0 = (chunk & 127) << 5;
        const __nv_bfloat16* Asrc = (pass < 2) ? g_xh : g_xl;
        const __nv_bfloat16* Bsrc = (pass == 1) ? g_wl : g_wh;
        uint32_t sb = sbase + stage * STG_BYTES;
        #pragma unroll
        for (int i = 0; i < 2; i++) {
            int idx = tid + i * 256;
            int r = idx >> 2, cb = idx & 3;
            cp_async16(sb + sw(r, cb), Asrc + (((size_t)(tm * 128 + r)) << 12) + k0 + cb * 8);
        }
        #pragma unroll
        for (int i = 0; i < 2; i++) {
            int idx = tid + i * 256;
            int r = idx >> 2, cb = idx & 3;
            cp_async16(sb + SMB_B + sw(r, cb), Bsrc + (((size_t)(tn * 128 + r)) << 12) + k0 + cb * 8);
        }
        CP_COMMIT();
    };

    float acc[2][8][4];
    #pragma unroll
    for (int mt = 0; mt < 2; mt++)
        #pragma unroll
        for (int nt = 0; nt < 8; nt++)
            #pragma unroll
            for (int e = 0; e < 4; e++) acc[mt][nt][e] = 0.f;

    load_chunk(0, 0);
    load_chunk(1, 1);

    #pragma unroll 1
    for (int it = 0; it < 384; it++) {
        if (it < 382) { CP_WAIT(1); } else { CP_WAIT(0); }
        __syncthreads();
        uint32_t sb = sbase + (it & 1) * STG_BYTES;
        #pragma unroll
        for (int kh = 0; kh < 2; kh++) {
            uint32_t a[2][4], b[4][4];
            ldsm4(a[0], sb + aoff[0][kh]);
            ldsm4(a[1], sb + aoff[1][kh]);
            #pragma unroll
            for (int p = 0; p < 4; p++) ldsm4(b[p], sb + boff[p][kh]);   // non-trans: B is [n][k]
            #pragma unroll
            for (int mt = 0; mt < 2; mt++)
                #pragma unroll
                for (int nt = 0; nt < 8; nt++)
                    mma16816(acc[mt][nt], a[mt], &b[nt >> 1][(nt & 1) * 2]);
        }
        __syncthreads();
        if (it + 2 < 384) load_chunk(it + 2, it & 1);
    }

    // ---- epilogue: scatter into g_gi[w][n][b] with bias ----
    #pragma unroll
    for (int mt = 0; mt < 2; mt++) {
        int row0 = tm * 128 + wm + mt * 16 + (lane >> 2);
        #pragma unroll
        for (int half = 0; half < 2; half++) {
            int row = row0 + half * 8;
            int w = row >> 5, b = row & 31;
            float* orow = g_gi + (size_t)w * G3 * 32 + b;
            #pragma unroll
            for (int nt = 0; nt < 8; nt++) {
                int n = tn * 128 + wn + nt * 8 + (lane & 3) * 2;
                float bia0 = __ldg(bih + n);
                float bia1 = __ldg(bih + n + 1);
                orow[(size_t)n * 32]       = acc[mt][nt][half * 2 + 0] + bia0;
                orow[(size_t)(n + 1) * 32] = acc[mt][nt][half * 2 + 1] + bia1;
            }
        }
    }
}

// ---------------- split-pipeline recurrence (identical to R4 passing version) ----------------
#define SMEM_BYTES ((24 * 1024 + 6 * 1024) * 4)

__global__ void __launch_bounds__(256, 1) recur2(
    const float* __restrict__ Whh, const float* __restrict__ bhh,
    const float* __restrict__ u, const float* __restrict__ Wpnf,
    const float* __restrict__ bpnf, const float* __restrict__ noise,
    float* __restrict__ out)
{
    extern __shared__ float sm[];
    const int bk = blockIdx.x;
    const int tid = threadIdx.x;
    const int lane = tid & 31;
    const int wp = tid >> 5;

    float* out_z  = out;
    float* out_mu = out + Bx * Wt * Zd;
    float* out_lv = out + 2 * Bx * Wt * Zd;
    const float u0 = u[0];

    if (bk < NHB) {
        float* s_whh = sm;
        float* s_red = sm + 24 * 1024;
        const int i0 = bk * 8;

        for (int idx = tid; idx < 24576; idx += 256) {
            int c = idx & 3;
            int rest = idx >> 2;
            int g = rest % 3;
            int t2 = rest / 3;
            int uu = t2 & 7;
            int kq = t2 >> 3;
            s_whh[idx] = Whh[(size_t)(g * Hd + i0 + uu) * Hd + kq * 4 + c];
        }
        __syncthreads();

        const int i = i0 + wp;
        const float bhr = bhh[i];
        const float bhz = bhh[Hd + i];
        const float bhn = bhh[2 * Hd + i];
        const int hoff = ((i >> 2) * 32 + lane) * 4 + (i & 3);
        const int kq0 = wp * 32;

        #pragma unroll 1
        for (int t = 0; t < Wt; t++) {
            if (tid == 0) {
                if (t > 0) wait_ge(&g_hprog, (unsigned)(NHB * t));
                if (t >= NSLOT) wait_ge(&g_zaprog, (unsigned)(NZB * (t - (NSLOT - 1))));
            }
            __syncthreads();

            const float* gib = g_gi + ((size_t)t * G3) * 32;
            float gir = gib[(size_t)(0 * Hd + i) * 32 + lane];
            float giz = gib[(size_t)(1 * Hd + i) * 32 + lane];
            float gin = gib[(size_t)(2 * Hd + i) * 32 + lane];
            const float* hb = g_hring + (size_t)(t & 7) * HB;
            float hold = ldcg_f(hb + hoff);

            unsigned long long acc[24];
            #pragma unroll
            for (int ug = 0; ug < 24; ug++) acc[ug] = 0ull;

            #pragma unroll 1
            for (int jb = 0; jb < 32; jb += 8) {
                ulonglong2 hv[8];
                #pragma unroll
                for (int j = 0; j < 8; j++)
                    hv[j] = ldcg_u2(hb + (size_t)((kq0 + jb + j) * 32 + lane) * 4);
                #pragma unroll
                for (int j = 0; j < 8; j++) {
                    const ulonglong2* wq = (const ulonglong2*)(s_whh + (size_t)(kq0 + jb + j) * 96);
                    #pragma unroll
                    for (int ug = 0; ug < 24; ug++) {
                        ulonglong2 w2 = wq[ug];
                        fma2(acc[ug], hv[j].x, w2.x);
                        fma2(acc[ug], hv[j].y, w2.y);
                    }
                }
            }
            #pragma unroll
            for (int ug = 0; ug < 24; ug++) {
                float2 p = unpack2(acc[ug]);
                s_red[(wp * 24 + ug) * 32 + lane] = p.x + p.y;
            }
            __syncthreads();

            float ar = 0.f, az = 0.f, an = 0.f;
            #pragma unroll
            for (int ww = 0; ww < 8; ww++) {
                ar += s_red[(ww * 24 + wp * 3 + 0) * 32 + lane];
                az += s_red[(ww * 24 + wp * 3 + 1) * 32 + lane];
                an += s_red[(ww * 24 + wp * 3 + 2) * 32 + lane];
            }
            float rg = 1.f / (1.f + expf(-(gir + ar + bhr)));
            float zg = 1.f / (1.f + expf(-(giz + az + bhz)));
            float ng = tanhf(gin + rg * (an + bhn));
            float hnew = (1.f - zg) * ng + zg * hold;
            stcg_f(g_hring + (size_t)((t + 1) & 7) * HB + hoff, hnew);

            __syncthreads();
            if (tid == 0) arrive(&g_hprog);
        }
    } else {
        const int zb = bk - NHB;
        const int q = zb * 8 + wp;
        const bool qa = (q < Zd);
        float* s_wm = sm + wp * 2272;
        float* s_ws = s_wm + 1136;
        float* s_pnf = sm + 8 * 2272 + wp * 104;

        if (qa) {
            for (int j = lane; j < ZH; j += 32) {
                s_wm[j] = g_Wmd[q * ZH + j];
                s_ws[j] = g_Wsd[q * ZH + j];
            }
            for (int j = lane; j < Zd; j += 32) s_pnf[j] = Wpnf[q * Zd + j];
        }
        __syncthreads();

        const float bm2 = qa ? g_bmu2[q] : 0.f;
        const float bs2 = qa ? g_bsig2[q] : 0.f;
        const float bpq = qa ? bpnf[q] : 0.f;
        const ulonglong2* wm2 = (const ulonglong2*)(s_wm + 100);
        const ulonglong2* ws2 = (const ulonglong2*)(s_ws + 100);

        #pragma unroll 1
        for (int t = 0; t < Wt; t++) {
            if (tid == 0) {
                wait_ge(&g_hprog, (unsigned)(NHB * (t + 1)));
                if (t > 0) wait_ge(&g_zbprog, (unsigned)(NZB * t));
            }
            __syncthreads();

            float zp = 0.f;
            if (qa) {
                float amz = 0.f, asz = 0.f;
                #pragma unroll 4
                for (int z2 = 0; z2 < Zd; z2++) {
                    float zv = ldcg_f(g_zT + z2 * 32 + lane);
                    amz = fmaf(zv, s_wm[z2], amz);
                    asz = fmaf(zv, s_ws[z2], asz);
                }
                const float* hb = g_hring + (size_t)((t + 1) & 7) * HB;
                unsigned long long am0 = 0, am1 = 0, as0 = 0, as1 = 0;
                #pragma unroll 1
                for (int c = 0; c < 256; c += 16) {
                    ulonglong2 hv[16];
                    #pragma unroll
                    for (int j = 0; j < 16; j++)
                        hv[j] = ldcg_u2(hb + (size_t)((c + j) * 32 + lane) * 4);
                    #pragma unroll
                    for (int j = 0; j < 16; j++) {
                        ulonglong2 m2 = wm2[c + j];
                        ulonglong2 s2 = ws2[c + j];
                        fma2(am0, hv[j].x, m2.x); fma2(am1, hv[j].y, m2.y);
                        fma2(as0, hv[j].x, s2.x); fma2(as1, hv[j].y, s2.y);
                    }
                }
                float m = bm2 + amz + hsum2(am0, am1);
                float s = bs2 + asz + hsum2(as0, as1);
                float lv = fmaxf(s, 0.f) + log1pf(expf(-fabsf(s)));
                float eps = noise[(size_t)(t * Bx + lane) * Zd + q];
                zp = m + expf(0.5f * lv) * eps;
                stcg_f(g_zpreT + q * 32 + lane, zp);
                out_mu[(size_t)(lane * Wt + t) * Zd + q] = m;
                out_lv[(size_t)(lane * Wt + t) * Zd + q] = lv;
            }
            __syncthreads();
            if (tid == 0) {
                arrive(&g_zaprog);
                wait_ge(&g_zaprog, (unsigned)(NZB * (t + 1)));
            }
            __syncthreads();

            if (qa) {
                float a0 = 0.f, a1 = 0.f;
                #pragma unroll 4
                for (int z2 = 0; z2 < Zd; z2 += 2) {
                    a0 = fmaf(ldcg_f(g_zpreT + (z2 + 0) * 32 + lane), s_pnf[z2 + 0], a0);
                    a1 = fmaf(ldcg_f(g_zpreT + (z2 + 1) * 32 + lane), s_pnf[z2 + 1], a1);
                }
                float zn = zp + u0 * tanhf((a0 + a1) + bpq);
                out_z[(size_t)(lane * Wt + t) * Zd + q] = zn;
                stcg_f(g_zT + q * 32 + lane, zn);
            }
            __syncthreads();
            if (tid == 0) arrive(&g_zbprog);
        }
    }
}

// ---------------- launch ----------------
extern "C" void kernel_launch(void* const* d_in, const int* in_sizes, int n_in,
                              void* d_out, int out_size)
{
    const float* x    = (const float*)d_in[0];
    const float* Wih  = (const float*)d_in[1];
    const float* Whh  = (const float*)d_in[2];
    const float* bih  = (const float*)d_in[3];
    const float* bhh  = (const float*)d_in[4];
    const float* Wd   = (const float*)d_in[5];
    const float* bd   = (const float*)d_in[6];
    const float* Wmu  = (const float*)d_in[7];
    const float* bmu  = (const float*)d_in[8];
    const float* Wsig = (const float*)d_in[9];
    const float* bsig = (const float*)d_in[10];
    const float* u    = (const float*)d_in[11];
    const float* Wpnf = (const float*)d_in[12];
    const float* bpnf = (const float*)d_in[13];
    const float* noise= (const float*)d_in[14];
    float* out = (float*)d_out;

    cudaFuncSetAttribute(recur2, cudaFuncAttributeMaxDynamicSharedMemorySize, SMEM_BYTES);

    prep_kernel<<<(Zd * ZH + 255) / 256, 256>>>(Wd, bd, Wmu, bmu, Wsig, bsig);
    conv_x<<<(8192 * 4096) / (8 * 256), 256>>>(x);
    conv_w<<<(3072 * 4096) / (8 * 256), 256>>>(Wih);
    gemm_mma<<<dim3(24, 64), 256>>>(bih);
    recur2<<<NHB + NZB, 256, SMEM_BYTES>>>(Whh, bhh, u, Wpnf, bpnf, noise, out);
}

// round 8
// speedup vs baseline: 2.3966x; 1.0251x over previous
#include <cuda_runtime.h>
#include <cuda_bf16.h>
#include <math.h>
#include <stdint.h>

#define Bx  32
#define Wt  256
#define IND 4096
#define Hd  1024
#define Zd  100
#define Dd  100
#define G3  3072
#define ZH  1124
#define NHB 128
#define NZB 13
#define HB  (Hd * Bx)
#define NSLOT 16

// ---------------- f32x2 packed-FMA helpers (recurrence) ----------------
__device__ __forceinline__ void fma2(unsigned long long& d, unsigned long long a, unsigned long long b) {
    asm("fma.rn.f32x2 %0, %1, %2, %0;" : "+l"(d) : "l"(a), "l"(b));
}
__device__ __forceinline__ float2 unpack2(unsigned long long v) {
    float2 r;
    asm("mov.b64 {%0, %1}, %2;" : "=f"(r.x), "=f"(r.y) : "l"(v));
    return r;
}
__device__ __forceinline__ float hsum2(unsigned long long a, unsigned long long b) {
    float2 p = unpack2(a), q = unpack2(b);
    return (p.x + p.y) + (q.x + q.y);
}

// ---------------- L2-coherent load/store + sync primitives ----------------
__device__ __forceinline__ ulonglong2 ldcg_u2(const void* p) {
    ulonglong2 v;
    asm volatile("ld.global.cg.v2.u64 {%0,%1},[%2];" : "=l"(v.x), "=l"(v.y) : "l"(p));
    return v;
}
__device__ __forceinline__ float ldcg_f(const float* p) {
    float v; asm volatile("ld.global.cg.f32 %0,[%1];" : "=f"(v) : "l"(p)); return v;
}
__device__ __forceinline__ void stcg_f(float* p, float v) {
    asm volatile("st.global.cg.f32 [%0],%1;" :: "l"(p), "f"(v));
}
__device__ __forceinline__ void arrive(unsigned* c) {
    asm volatile("red.release.gpu.global.add.u32 [%0],%1;" :: "l"(c), "r"(1u) : "memory");
}
__device__ __forceinline__ void wait_ge(const unsigned* c, unsigned target) {
    unsigned v;
    asm volatile("ld.acquire.gpu.global.u32 %0,[%1];" : "=r"(v) : "l"(c) : "memory");
    while ((int)(v - target) < 0) {
        __nanosleep(32);
        asm volatile("ld.acquire.gpu.global.u32 %0,[%1];" : "=r"(v) : "l"(c) : "memory");
    }
}

// ---------------- mma.sync helpers ----------------
__device__ __forceinline__ uint32_t smem_u32(const void* p) {
    uint32_t a;
    asm("{ .reg .u64 t; cvta.to.shared.u64 t, %1; cvt.u32.u64 %0, t; }" : "=r"(a) : "l"(p));
    return a;
}
__device__ __forceinline__ void ldsm4(uint32_t* r, uint32_t addr) {
    asm volatile("ldmatrix.sync.aligned.m8n8.x4.shared.b16 {%0,%1,%2,%3},[%4];"
                 : "=r"(r[0]), "=r"(r[1]), "=r"(r[2]), "=r"(r[3]) : "r"(addr));
}
__device__ __forceinline__ void mma16816(float* c, const uint32_t* a, const uint32_t* b) {
    asm volatile("mma.sync.aligned.m16n8k16.row.col.f32.bf16.bf16.f32 "
                 "{%0,%1,%2,%3},{%4,%5,%6,%7},{%8,%9},{%0,%1,%2,%3};"
                 : "+f"(c[0]), "+f"(c[1]), "+f"(c[2]), "+f"(c[3])
                 : "r"(a[0]), "r"(a[1]), "r"(a[2]), "r"(a[3]), "r"(b[0]), "r"(b[1]));
}
__device__ __forceinline__ void cp_async16(uint32_t saddr, const void* gaddr) {
    asm volatile("cp.async.cg.shared.global [%0],[%1],16;" :: "r"(saddr), "l"(gaddr));
}
#define CP_COMMIT() asm volatile("cp.async.commit_group;" ::: "memory")
#define CP_WAIT(n)  asm volatile("cp.async.wait_group %0;" :: "n"(n) : "memory")

// ---------------- device globals ----------------
__device__ __align__(16) float g_gi[25165824];        // [W][3H][B]
__device__ __align__(16) __nv_bfloat16 g_xh[8192 * 4096];
__device__ __align__(16) __nv_bfloat16 g_xl[8192 * 4096];
__device__ __align__(16) __nv_bfloat16 g_wh[3072 * 4096];
__device__ __align__(16) __nv_bfloat16 g_wl[3072 * 4096];
__device__ __align__(16) float g_hring[NSLOT * HB];
__device__ __align__(16) float g_zT[Zd * Bx];
__device__ __align__(16) float g_zpreT[Zd * Bx];
__device__ __align__(16) float g_Wmd[Zd * ZH];
__device__ __align__(16) float g_Wsd[Zd * ZH];
__device__ float g_bmu2[Zd];
__device__ float g_bsig2[Zd];
__device__ unsigned g_hprog;
__device__ unsigned g_zaprog;
__device__ unsigned g_zbprog;

// ---------------- prep ----------------
__global__ void prep_kernel(const float* __restrict__ Wd, const float* __restrict__ bd,
                            const float* __restrict__ Wmu, const float* __restrict__ bmu,
                            const float* __restrict__ Wsig, const float* __restrict__ bsig)
{
    int idx = blockIdx.x * blockDim.x + threadIdx.x;
    if (idx < Zd * ZH) {
        int q = idx / ZH, j = idx % ZH;
        float am = 0.f, as = 0.f;
        for (int d = 0; d < Dd; d++) {
            float wd = Wd[(size_t)d * ZH + j];
            am = fmaf(Wmu[q * Dd + d], wd, am);
            as = fmaf(Wsig[q * Dd + d], wd, as);
        }
        g_Wmd[idx] = am;
        g_Wsd[idx] = as;
    }
    if (idx < Zd) {
        float am = bmu[idx], as = bsig[idx];
        for (int d = 0; d < Dd; d++) {
            am = fmaf(Wmu[idx * Dd + d], bd[d], am);
            as = fmaf(Wsig[idx * Dd + d], bd[d], as);
        }
        g_bmu2[idx] = am;
        g_bsig2[idx] = as;
    }
    if (idx < HB) g_hring[idx] = 0.f;
    if (idx < Zd * Bx) g_zT[idx] = 0.f;
    if (idx == 0) { g_hprog = 0u; g_zaprog = 0u; g_zbprog = 0u; }
}

// ---------------- split conversions ----------------
__device__ __forceinline__ void split8(const float* s, __nv_bfloat16* h, __nv_bfloat16* l) {
    #pragma unroll
    for (int i = 0; i < 8; i++) {
        float v = s[i];
        __nv_bfloat16 hb = __float2bfloat16_rn(v);
        h[i] = hb;
        l[i] = __float2bfloat16_rn(v - __bfloat162float(hb));
    }
}

__global__ void __launch_bounds__(256) conv_x(const float* __restrict__ x) {
    size_t idx = ((size_t)blockIdx.x * 256 + threadIdx.x) * 8;
    int m = (int)(idx >> 12), k = (int)(idx & 4095);
    int b = m & 31, w = m >> 5;
    float s[8];
    *(float4*)(s)     = *(const float4*)(x + ((size_t)(b * Wt + w) << 12) + k);
    *(float4*)(s + 4) = *(const float4*)(x + ((size_t)(b * Wt + w) << 12) + k + 4);
    __nv_bfloat16 h[8], l[8];
    split8(s, h, l);
    *(uint4*)(g_xh + idx) = *(uint4*)h;
    *(uint4*)(g_xl + idx) = *(uint4*)l;
}

__global__ void __launch_bounds__(256) conv_w(const float* __restrict__ Wih) {
    size_t idx = ((size_t)blockIdx.x * 256 + threadIdx.x) * 8;
    float s[8];
    *(float4*)(s)     = *(const float4*)(Wih + idx);
    *(float4*)(s + 4) = *(const float4*)(Wih + idx + 4);
    __nv_bfloat16 h[8], l[8];
    split8(s, h, l);
    *(uint4*)(g_wh + idx) = *(uint4*)h;
    *(uint4*)(g_wl + idx) = *(uint4*)l;
}

// ---------------- mma.sync GEMM: 4-stage cp.async ring, 1 bar/iteration ----------------
#define NSTG 4
#define STG_BYTES 16384          // A 8KB + B 8KB per stage
#define SMB_B 8192
#define GEMM_SMEM (NSTG * STG_BYTES)   // 64KB dynamic

__global__ void __launch_bounds__(256, 2) gemm_mma(const float* __restrict__ bih) {
    extern __shared__ __align__(128) char smg[];
    const uint32_t sbase = smem_u32(smg);
    const int tid = threadIdx.x;
    const int lane = tid & 31;
    const int wid = tid >> 5;
    const int tn = blockIdx.x;        // 0..23
    const int tm = blockIdx.y;        // 0..63
    const int wm = (wid & 3) * 32;    // warp M offset in tile
    const int wn = (wid >> 2) * 64;   // warp N offset in tile

    // swizzled byte offset inside a 128x32-bf16 tile (64B rows)
    auto sw = [](int r, int cb) -> uint32_t {
        return (uint32_t)(r * 64 + ((cb ^ ((r >> 1) & 3)) << 4));
    };

    // ---- per-lane ldmatrix addresses (offsets within stage) ----
    uint32_t aoff[2][2], boff[4][2];
    {
        int ml = wm + (lane & 15);
        #pragma unroll
        for (int mt = 0; mt < 2; mt++)
            #pragma unroll
            for (int kh = 0; kh < 2; kh++)
                aoff[mt][kh] = sw(ml + mt * 16, kh * 2 + (lane >> 4));
        int nl = wn + ((lane >> 4) << 3) + (lane & 7);
        #pragma unroll
        for (int p = 0; p < 4; p++)
            #pragma unroll
            for (int kh = 0; kh < 2; kh++)
                boff[p][kh] = (uint32_t)SMB_B + sw(nl + p * 16, kh * 2 + ((lane >> 3) & 1));
    }

    // ---- loader ----
    auto load_chunk = [&](int chunk, int stage) {
        int pass = chunk >> 7;
        int k0 = (chunk & 127) << 5;
        const __nv_bfloat16* Asrc = (pass < 2) ? g_xh : g_xl;
        const __nv_bfloat16* Bsrc = (pass == 1) ? g_wl : g_wh;
        uint32_t sb = sbase + stage * STG_BYTES;
        #pragma unroll
        for (int i = 0; i < 2; i++) {
            int idx = tid + i * 256;
            int r = idx >> 2, cb = idx & 3;
            cp_async16(sb + sw(r, cb), Asrc + (((size_t)(tm * 128 + r)) << 12) + k0 + cb * 8);
        }
        #pragma unroll
        for (int i = 0; i < 2; i++) {
            int idx = tid + i * 256;
            int r = idx >> 2, cb = idx & 3;
            cp_async16(sb + SMB_B + sw(r, cb), Bsrc + (((size_t)(tn * 128 + r)) << 12) + k0 + cb * 8);
        }
        CP_COMMIT();
    };

    float acc[2][8][4];
    #pragma unroll
    for (int mt = 0; mt < 2; mt++)
        #pragma unroll
        for (int nt = 0; nt < 8; nt++)
            #pragma unroll
            for (int e = 0; e < 4; e++) acc[mt][nt][e] = 0.f;

    load_chunk(0, 0);
    load_chunk(1, 1);
    load_chunk(2, 2);

    #pragma unroll 1
    for (int it = 0; it < 384; it++) {
        CP_WAIT(2);                // chunk `it` complete (≤2 younger groups outstanding)
        __syncthreads();           // single bar: all warps done with chunk it-1 (slot reused by it+3)
        uint32_t sb = sbase + (it & 3) * STG_BYTES;
        #pragma unroll
        for (int kh = 0; kh < 2; kh++) {
            uint32_t a[2][4], b[4][4];
            ldsm4(a[0], sb + aoff[0][kh]);
            ldsm4(a[1], sb + aoff[1][kh]);
            #pragma unroll
            for (int p = 0; p < 4; p++) ldsm4(b[p], sb + boff[p][kh]);   // non-trans: B is [n][k]
            #pragma unroll
            for (int mt = 0; mt < 2; mt++)
                #pragma unroll
                for (int nt = 0; nt < 8; nt++)
                    mma16816(acc[mt][nt], a[mt], &b[nt >> 1][(nt & 1) * 2]);
        }
        if (it + 3 < 384) load_chunk(it + 3, (it + 3) & 3);
    }

    // ---- epilogue: scatter into g_gi[w][n][b] with bias ----
    #pragma unroll
    for (int mt = 0; mt < 2; mt++) {
        int row0 = tm * 128 + wm + mt * 16 + (lane >> 2);
        #pragma unroll
        for (int half = 0; half < 2; half++) {
            int row = row0 + half * 8;
            int w = row >> 5, b = row & 31;
            float* orow = g_gi + (size_t)w * G3 * 32 + b;
            #pragma unroll
            for (int nt = 0; nt < 8; nt++) {
                int n = tn * 128 + wn + nt * 8 + (lane & 3) * 2;
                float bia0 = __ldg(bih + n);
                float bia1 = __ldg(bih + n + 1);
                orow[(size_t)n * 32]       = acc[mt][nt][half * 2 + 0] + bia0;
                orow[(size_t)(n + 1) * 32] = acc[mt][nt][half * 2 + 1] + bia1;
            }
        }
    }
}

// ---------------- split-pipeline recurrence (R4 logic, 16-deep ring) ----------------
#define SMEM_BYTES ((24 * 1024 + 6 * 1024) * 4)

__global__ void __launch_bounds__(256, 1) recur2(
    const float* __restrict__ Whh, const float* __restrict__ bhh,
    const float* __restrict__ u, const float* __restrict__ Wpnf,
    const float* __restrict__ bpnf, const float* __restrict__ noise,
    float* __restrict__ out)
{
    extern __shared__ float sm[];
    const int bk = blockIdx.x;
    const int tid = threadIdx.x;
    const int lane = tid & 31;
    const int wp = tid >> 5;

    float* out_z  = out;
    float* out_mu = out + Bx * Wt * Zd;
    float* out_lv = out + 2 * Bx * Wt * Zd;
    const float u0 = u[0];

    if (bk < NHB) {
        float* s_whh = sm;
        float* s_red = sm + 24 * 1024;
        const int i0 = bk * 8;

        for (int idx = tid; idx < 24576; idx += 256) {
            int c = idx & 3;
            int rest = idx >> 2;
            int g = rest % 3;
            int t2 = rest / 3;
            int uu = t2 & 7;
            int kq = t2 >> 3;
            s_whh[idx] = Whh[(size_t)(g * Hd + i0 + uu) * Hd + kq * 4 + c];
        }
        __syncthreads();

        const int i = i0 + wp;
        const float bhr = bhh[i];
        const float bhz = bhh[Hd + i];
        const float bhn = bhh[2 * Hd + i];
        const int hoff = ((i >> 2) * 32 + lane) * 4 + (i & 3);
        const int kq0 = wp * 32;

        #pragma unroll 1
        for (int t = 0; t < Wt; t++) {
            if (tid == 0) {
                if (t > 0) wait_ge(&g_hprog, (unsigned)(NHB * t));
                if (t >= NSLOT) wait_ge(&g_zaprog, (unsigned)(NZB * (t - (NSLOT - 1))));
            }
            __syncthreads();

            const float* gib = g_gi + ((size_t)t * G3) * 32;
            float gir = gib[(size_t)(0 * Hd + i) * 32 + lane];
            float giz = gib[(size_t)(1 * Hd + i) * 32 + lane];
            float gin = gib[(size_t)(2 * Hd + i) * 32 + lane];
            const float* hb = g_hring + (size_t)(t & (NSLOT - 1)) * HB;
            float hold = ldcg_f(hb + hoff);

            unsigned long long acc[24];
            #pragma unroll
            for (int ug = 0; ug < 24; ug++) acc[ug] = 0ull;

            #pragma unroll 1
            for (int jb = 0; jb < 32; jb += 8) {
                ulonglong2 hv[8];
                #pragma unroll
                for (int j = 0; j < 8; j++)
                    hv[j] = ldcg_u2(hb + (size_t)((kq0 + jb + j) * 32 + lane) * 4);
                #pragma unroll
                for (int j = 0; j < 8; j++) {
                    const ulonglong2* wq = (const ulonglong2*)(s_whh + (size_t)(kq0 + jb + j) * 96);
                    #pragma unroll
                    for (int ug = 0; ug < 24; ug++) {
                        ulonglong2 w2 = wq[ug];
                        fma2(acc[ug], hv[j].x, w2.x);
                        fma2(acc[ug], hv[j].y, w2.y);
                    }
                }
            }
            #pragma unroll
            for (int ug = 0; ug < 24; ug++) {
                float2 p = unpack2(acc[ug]);
                s_red[(wp * 24 + ug) * 32 + lane] = p.x + p.y;
            }
            __syncthreads();

            float ar = 0.f, az = 0.f, an = 0.f;
            #pragma unroll
            for (int ww = 0; ww < 8; ww++) {
                ar += s_red[(ww * 24 + wp * 3 + 0) * 32 + lane];
                az += s_red[(ww * 24 + wp * 3 + 1) * 32 + lane];
                an += s_red[(ww * 24 + wp * 3 + 2) * 32 + lane];
            }
            float rg = 1.f / (1.f + expf(-(gir + ar + bhr)));
            float zg = 1.f / (1.f + expf(-(giz + az + bhz)));
            float ng = tanhf(gin + rg * (an + bhn));
            float hnew = (1.f - zg) * ng + zg * hold;
            stcg_f(g_hring + (size_t)((t + 1) & (NSLOT - 1)) * HB + hoff, hnew);

            __syncthreads();
            if (tid == 0) arrive(&g_hprog);
        }
    } else {
        const int zb = bk - NHB;
        const int q = zb * 8 + wp;
        const bool qa = (q < Zd);
        float* s_wm = sm + wp * 2272;
        float* s_ws = s_wm + 1136;
        float* s_pnf = sm + 8 * 2272 + wp * 104;

        if (qa) {
            for (int j = lane; j < ZH; j += 32) {
                s_wm[j] = g_Wmd[q * ZH + j];
                s_ws[j] = g_Wsd[q * ZH + j];
            }
            for (int j = lane; j < Zd; j += 32) s_pnf[j] = Wpnf[q * Zd + j];
        }
        __syncthreads();

        const float bm2 = qa ? g_bmu2[q] : 0.f;
        const float bs2 = qa ? g_bsig2[q] : 0.f;
        const float bpq = qa ? bpnf[q] : 0.f;
        const ulonglong2* wm2 = (const ulonglong2*)(s_wm + 100);
        const ulonglong2* ws2 = (const ulonglong2*)(s_ws + 100);

        #pragma unroll 1
        for (int t = 0; t < Wt; t++) {
            if (tid == 0) {
                wait_ge(&g_hprog, (unsigned)(NHB * (t + 1)));
                if (t > 0) wait_ge(&g_zbprog, (unsigned)(NZB * t));
            }
            __syncthreads();

            float zp = 0.f;
            if (qa) {
                float amz = 0.f, asz = 0.f;
                #pragma unroll 4
                for (int z2 = 0; z2 < Zd; z2++) {
                    float zv = ldcg_f(g_zT + z2 * 32 + lane);
                    amz = fmaf(zv, s_wm[z2], amz);
                    asz = fmaf(zv, s_ws[z2], asz);
                }
                const float* hb = g_hring + (size_t)((t + 1) & (NSLOT - 1)) * HB;
                unsigned long long am0 = 0, am1 = 0, as0 = 0, as1 = 0;
                #pragma unroll 1
                for (int c = 0; c < 256; c += 16) {
                    ulonglong2 hv[16];
                    #pragma unroll
                    for (int j = 0; j < 16; j++)
                        hv[j] = ldcg_u2(hb + (size_t)((c + j) * 32 + lane) * 4);
                    #pragma unroll
                    for (int j = 0; j < 16; j++) {
                        ulonglong2 m2 = wm2[c + j];
                        ulonglong2 s2 = ws2[c + j];
                        fma2(am0, hv[j].x, m2.x); fma2(am1, hv[j].y, m2.y);
                        fma2(as0, hv[j].x, s2.x); fma2(as1, hv[j].y, s2.y);
                    }
                }
                float m = bm2 + amz + hsum2(am0, am1);
                float s = bs2 + asz + hsum2(as0, as1);
                float lv = fmaxf(s, 0.f) + log1pf(expf(-fabsf(s)));
                float eps = noise[(size_t)(t * Bx + lane) * Zd + q];
                zp = m + expf(0.5f * lv) * eps;
                stcg_f(g_zpreT + q * 32 + lane, zp);
                out_mu[(size_t)(lane * Wt + t) * Zd + q] = m;
                out_lv[(size_t)(lane * Wt + t) * Zd + q] = lv;
            }
            __syncthreads();
            if (tid == 0) {
                arrive(&g_zaprog);
                wait_ge(&g_zaprog, (unsigned)(NZB * (t + 1)));
            }
            __syncthreads();

            if (qa) {
                float a0 = 0.f, a1 = 0.f;
                #pragma unroll 4
                for (int z2 = 0; z2 < Zd; z2 += 2) {
                    a0 = fmaf(ldcg_f(g_zpreT + (z2 + 0) * 32 + lane), s_pnf[z2 + 0], a0);
                    a1 = fmaf(ldcg_f(g_zpreT + (z2 + 1) * 32 + lane), s_pnf[z2 + 1], a1);
                }
                float zn = zp + u0 * tanhf((a0 + a1) + bpq);
                out_z[(size_t)(lane * Wt + t) * Zd + q] = zn;
                stcg_f(g_zT + q * 32 + lane, zn);
            }
            __syncthreads();
            if (tid == 0) arrive(&g_zbprog);
        }
    }
}

// ---------------- launch ----------------
extern "C" void kernel_launch(void* const* d_in, const int* in_sizes, int n_in,
                              void* d_out, int out_size)
{
    const float* x    = (const float*)d_in[0];
    const float* Wih  = (const float*)d_in[1];
    const float* Whh  = (const float*)d_in[2];
    const float* bih  = (const float*)d_in[3];
    const float* bhh  = (const float*)d_in[4];
    const float* Wd   = (const float*)d_in[5];
    const float* bd   = (const float*)d_in[6];
    const float* Wmu  = (const float*)d_in[7];
    const float* bmu  = (const float*)d_in[8];
    const float* Wsig = (const float*)d_in[9];
    const float* bsig = (const float*)d_in[10];
    const float* u    = (const float*)d_in[11];
    const float* Wpnf = (const float*)d_in[12];
    const float* bpnf = (const float*)d_in[13];
    const float* noise= (const float*)d_in[14];
    float* out = (float*)d_out;

    cudaFuncSetAttribute(recur2, cudaFuncAttributeMaxDynamicSharedMemorySize, SMEM_BYTES);
    cudaFuncSetAttribute(gemm_mma, cudaFuncAttributeMaxDynamicSharedMemorySize, GEMM_SMEM);

    prep_kernel<<<(Zd * ZH + 255) / 256, 256>>>(Wd, bd, Wmu, bmu, Wsig, bsig);
    conv_x<<<(8192 * 4096) / (8 * 256), 256>>>(x);
    conv_w<<<(3072 * 4096) / (8 * 256), 256>>>(Wih);
    gemm_mma<<<dim3(24, 64), 256, GEMM_SMEM>>>(bih);
    recur2<<<NHB + NZB, 256, SMEM_BYTES>>>(Whh, bhh, u, Wpnf, bpnf, noise, out);
}

// round 9
// speedup vs baseline: 2.4817x; 1.0355x over previous
#include <cuda_runtime.h>
#include <cuda_bf16.h>
#include <math.h>
#include <stdint.h>

#define Bx  32
#define Wt  256
#define IND 4096
#define Hd  1024
#define Zd  100
#define Dd  100
#define G3  3072
#define ZH  1124
#define NHB 128
#define NZB 13
#define HB  (Hd * Bx)
#define NSLOT 16

// ---------------- f32x2 packed-FMA helpers (recurrence) ----------------
__device__ __forceinline__ void fma2(unsigned long long& d, unsigned long long a, unsigned long long b) {
    asm("fma.rn.f32x2 %0, %1, %2, %0;" : "+l"(d) : "l"(a), "l"(b));
}
__device__ __forceinline__ float2 unpack2(unsigned long long v) {
    float2 r;
    asm("mov.b64 {%0, %1}, %2;" : "=f"(r.x), "=f"(r.y) : "l"(v));
    return r;
}
__device__ __forceinline__ float hsum2(unsigned long long a, unsigned long long b) {
    float2 p = unpack2(a), q = unpack2(b);
    return (p.x + p.y) + (q.x + q.y);
}

// ---------------- L2-coherent load/store + sync primitives ----------------
__device__ __forceinline__ ulonglong2 ldcg_u2(const void* p) {
    ulonglong2 v;
    asm volatile("ld.global.cg.v2.u64 {%0,%1},[%2];" : "=l"(v.x), "=l"(v.y) : "l"(p));
    return v;
}
__device__ __forceinline__ float ldcg_f(const float* p) {
    float v; asm volatile("ld.global.cg.f32 %0,[%1];" : "=f"(v) : "l"(p)); return v;
}
__device__ __forceinline__ void stcg_f(float* p, float v) {
    asm volatile("st.global.cg.f32 [%0],%1;" :: "l"(p), "f"(v));
}
__device__ __forceinline__ void arrive(unsigned* c) {
    asm volatile("red.release.gpu.global.add.u32 [%0],%1;" :: "l"(c), "r"(1u) : "memory");
}
__device__ __forceinline__ void wait_ge(const unsigned* c, unsigned target) {
    unsigned v;
    asm volatile("ld.acquire.gpu.global.u32 %0,[%1];" : "=r"(v) : "l"(c) : "memory");
    while ((int)(v - target) < 0) {
        __nanosleep(32);
        asm volatile("ld.acquire.gpu.global.u32 %0,[%1];" : "=r"(v) : "l"(c) : "memory");
    }
}

// ---------------- mma.sync helpers ----------------
__device__ __forceinline__ uint32_t smem_u32(const void* p) {
    uint32_t a;
    asm("{ .reg .u64 t; cvta.to.shared.u64 t, %1; cvt.u32.u64 %0, t; }" : "=r"(a) : "l"(p));
    return a;
}
__device__ __forceinline__ void ldsm4(uint32_t* r, uint32_t addr) {
    asm volatile("ldmatrix.sync.aligned.m8n8.x4.shared.b16 {%0,%1,%2,%3},[%4];"
                 : "=r"(r[0]), "=r"(r[1]), "=r"(r[2]), "=r"(r[3]) : "r"(addr));
}
__device__ __forceinline__ void mma16816(float* c, const uint32_t* a, const uint32_t* b) {
    asm volatile("mma.sync.aligned.m16n8k16.row.col.f32.bf16.bf16.f32 "
                 "{%0,%1,%2,%3},{%4,%5,%6,%7},{%8,%9},{%0,%1,%2,%3};"
                 : "+f"(c[0]), "+f"(c[1]), "+f"(c[2]), "+f"(c[3])
                 : "r"(a[0]), "r"(a[1]), "r"(a[2]), "r"(a[3]), "r"(b[0]), "r"(b[1]));
}
__device__ __forceinline__ void cp_async16(uint32_t saddr, const void* gaddr) {
    asm volatile("cp.async.cg.shared.global [%0],[%1],16;" :: "r"(saddr), "l"(gaddr));
}
#define CP_COMMIT() asm volatile("cp.async.commit_group;" ::: "memory")
#define CP_WAIT(n)  asm volatile("cp.async.wait_group %0;" :: "n"(n) : "memory")

// ---------------- device globals ----------------
__device__ __align__(16) float g_gi [25165824];       // pass0: xh*wh + bias   [W][3H][B]
__device__ __align__(16) float g_giB[25165824];       // pass1: xh*wl
__device__ __align__(16) float g_giC[25165824];       // pass2: xl*wh
__device__ __align__(16) __nv_bfloat16 g_xh[8192 * 4096];
__device__ __align__(16) __nv_bfloat16 g_xl[8192 * 4096];
__device__ __align__(16) __nv_bfloat16 g_wh[3072 * 4096];
__device__ __align__(16) __nv_bfloat16 g_wl[3072 * 4096];
__device__ __align__(16) float g_hring[NSLOT * HB];
__device__ __align__(16) float g_zT[Zd * Bx];
__device__ __align__(16) float g_zpreT[Zd * Bx];
__device__ __align__(16) float g_Wmd[Zd * ZH];
__device__ __align__(16) float g_Wsd[Zd * ZH];
__device__ float g_bmu2[Zd];
__device__ float g_bsig2[Zd];
__device__ unsigned g_hprog;
__device__ unsigned g_zaprog;
__device__ unsigned g_zbprog;

// ---------------- prep ----------------
__global__ void prep_kernel(const float* __restrict__ Wd, const float* __restrict__ bd,
                            const float* __restrict__ Wmu, const float* __restrict__ bmu,
                            const float* __restrict__ Wsig, const float* __restrict__ bsig)
{
    int idx = blockIdx.x * blockDim.x + threadIdx.x;
    if (idx < Zd * ZH) {
        int q = idx / ZH, j = idx % ZH;
        float am = 0.f, as = 0.f;
        for (int d = 0; d < Dd; d++) {
            float wd = Wd[(size_t)d * ZH + j];
            am = fmaf(Wmu[q * Dd + d], wd, am);
            as = fmaf(Wsig[q * Dd + d], wd, as);
        }
        g_Wmd[idx] = am;
        g_Wsd[idx] = as;
    }
    if (idx < Zd) {
        float am = bmu[idx], as = bsig[idx];
        for (int d = 0; d < Dd; d++) {
            am = fmaf(Wmu[idx * Dd + d], bd[d], am);
            as = fmaf(Wsig[idx * Dd + d], bd[d], as);
        }
        g_bmu2[idx] = am;
        g_bsig2[idx] = as;
    }
    if (idx < HB) g_hring[idx] = 0.f;
    if (idx < Zd * Bx) g_zT[idx] = 0.f;
    if (idx == 0) { g_hprog = 0u; g_zaprog = 0u; g_zbprog = 0u; }
}

// ---------------- split conversions ----------------
__device__ __forceinline__ void split8(const float* s, __nv_bfloat16* h, __nv_bfloat16* l) {
    #pragma unroll
    for (int i = 0; i < 8; i++) {
        float v = s[i];
        __nv_bfloat16 hb = __float2bfloat16_rn(v);
        h[i] = hb;
        l[i] = __float2bfloat16_rn(v - __bfloat162float(hb));
    }
}

__global__ void __launch_bounds__(256) conv_x(const float* __restrict__ x) {
    size_t idx = ((size_t)blockIdx.x * 256 + threadIdx.x) * 8;
    int m = (int)(idx >> 12), k = (int)(idx & 4095);
    int b = m & 31, w = m >> 5;
    float s[8];
    *(float4*)(s)     = *(const float4*)(x + ((size_t)(b * Wt + w) << 12) + k);
    *(float4*)(s + 4) = *(const float4*)(x + ((size_t)(b * Wt + w) << 12) + k + 4);
    __nv_bfloat16 h[8], l[8];
    split8(s, h, l);
    *(uint4*)(g_xh + idx) = *(uint4*)h;
    *(uint4*)(g_xl + idx) = *(uint4*)l;
}

__global__ void __launch_bounds__(256) conv_w(const float* __restrict__ Wih) {
    size_t idx = ((size_t)blockIdx.x * 256 + threadIdx.x) * 8;
    float s[8];
    *(float4*)(s)     = *(const float4*)(Wih + idx);
    *(float4*)(s + 4) = *(const float4*)(Wih + idx + 4);
    __nv_bfloat16 h[8], l[8];
    split8(s, h, l);
    *(uint4*)(g_wh + idx) = *(uint4*)h;
    *(uint4*)(g_wl + idx) = *(uint4*)l;
}

// ---------------- persistent mma.sync GEMM over (tile, pass) work items ----------------
// 296 CTAs; items = 3 passes x (64 tm x 24 tn) = 4608. CTA tile 128x128, BK=64,
// 3-stage cp.async ring (32KB/stage, 96KB total, 2 CTAs/SM).
#define NITEM 4608
#define GRID_P 296
#define STG64 32768
#define SMB_B64 16384
#define GEMM_SMEM (3 * STG64)     // 96KB

__global__ void __launch_bounds__(256, 2) gemm_mma(const float* __restrict__ bih) {
    extern __shared__ __align__(128) char smg[];
    const uint32_t sbase = smem_u32(smg);
    const int tid = threadIdx.x;
    const int lane = tid & 31;
    const int wid = tid >> 5;
    const int wm = (wid & 3) * 32;
    const int wn = (wid >> 2) * 64;

    // swizzled byte offset inside a 128x64-bf16 tile (128B rows, XOR-8 swizzle)
    auto sw = [](int r, int cb) -> uint32_t {
        return (uint32_t)(r * 128 + ((cb ^ (r & 7)) << 4));
    };

    // per-lane ldmatrix offsets (within stage); kh = 0..3 (K16 groups of BK=64)
    uint32_t aoff[2][4], boff[4][4];
    {
        int ml = wm + (lane & 15);
        #pragma unroll
        for (int mt = 0; mt < 2; mt++)
            #pragma unroll
            for (int kh = 0; kh < 4; kh++)
                aoff[mt][kh] = sw(ml + mt * 16, kh * 2 + (lane >> 4));
        int nl = wn + ((lane >> 4) << 3) + (lane & 7);
        #pragma unroll
        for (int p = 0; p < 4; p++)
            #pragma unroll
            for (int kh = 0; kh < 4; kh++)
                boff[p][kh] = (uint32_t)SMB_B64 + sw(nl + p * 16, kh * 2 + ((lane >> 3) & 1));
    }

    #pragma unroll 1
    for (int j = blockIdx.x; j < NITEM; j += GRID_P) {
        const int pass = j / 1536;
        const int rem  = j % 1536;
        const int tm   = rem / 24;
        const int tn   = rem % 24;
        const __nv_bfloat16* Asrc = (pass < 2) ? g_xh : g_xl;
        const __nv_bfloat16* Bsrc = (pass == 1) ? g_wl : g_wh;

        auto load_st = [&](int it, int slot) {
            int k0 = it << 6;
            uint32_t sb = sbase + slot * STG64;
            #pragma unroll
            for (int i = 0; i < 4; i++) {
                int idx = tid + i * 256;           // 0..1023
                int r = idx >> 3, cb = idx & 7;
                cp_async16(sb + sw(r, cb), Asrc + (((size_t)(tm * 128 + r)) << 12) + k0 + cb * 8);
            }
            #pragma unroll
            for (int i = 0; i < 4; i++) {
                int idx = tid + i * 256;
                int r = idx >> 3, cb = idx & 7;
                cp_async16(sb + SMB_B64 + sw(r, cb), Bsrc + (((size_t)(tn * 128 + r)) << 12) + k0 + cb * 8);
            }
            CP_COMMIT();
        };

        float acc[2][8][4];
        #pragma unroll
        for (int mt = 0; mt < 2; mt++)
            #pragma unroll
            for (int nt = 0; nt < 8; nt++)
                #pragma unroll
                for (int e = 0; e < 4; e++) acc[mt][nt][e] = 0.f;

        __syncthreads();          // protect stage slots from previous item's consumers
        load_st(0, 0);
        load_st(1, 1);

        #pragma unroll 1
        for (int it = 0; it < 64; it++) {
            if (it >= 62) { CP_WAIT(0); } else { CP_WAIT(1); }
            __syncthreads();
            int slot = it % 3;
            uint32_t sb = sbase + slot * STG64;
            #pragma unroll
            for (int kh = 0; kh < 4; kh++) {
                uint32_t a[2][4], b[4][4];
                ldsm4(a[0], sb + aoff[0][kh]);
                ldsm4(a[1], sb + aoff[1][kh]);
                #pragma unroll
                for (int p = 0; p < 4; p++) ldsm4(b[p], sb + boff[p][kh]);
                #pragma unroll
                for (int mt = 0; mt < 2; mt++)
                    #pragma unroll
                    for (int nt = 0; nt < 8; nt++)
                        mma16816(acc[mt][nt], a[mt], &b[nt >> 1][(nt & 1) * 2]);
            }
            if (it + 2 < 64) load_st(it + 2, (it + 2) % 3);
        }

        // epilogue: pass-private buffer, bias only on pass 0
        float* gout = (pass == 0) ? g_gi : ((pass == 1) ? g_giB : g_giC);
        #pragma unroll
        for (int mt = 0; mt < 2; mt++) {
            int row0 = tm * 128 + wm + mt * 16 + (lane >> 2);
            #pragma unroll
            for (int half = 0; half < 2; half++) {
                int row = row0 + half * 8;
                int w = row >> 5, b = row & 31;
                float* orow = gout + (size_t)w * G3 * 32 + b;
                #pragma unroll
                for (int nt = 0; nt < 8; nt++) {
                    int n = tn * 128 + wn + nt * 8 + (lane & 3) * 2;
                    float bia0 = (pass == 0) ? __ldg(bih + n) : 0.f;
                    float bia1 = (pass == 0) ? __ldg(bih + n + 1) : 0.f;
                    orow[(size_t)n * 32]       = acc[mt][nt][half * 2 + 0] + bia0;
                    orow[(size_t)(n + 1) * 32] = acc[mt][nt][half * 2 + 1] + bia1;
                }
            }
        }
    }
}

// ---------------- split-pipeline recurrence (gi = sum of 3 buffers) ----------------
#define SMEM_BYTES ((24 * 1024 + 6 * 1024) * 4)

__global__ void __launch_bounds__(256, 1) recur2(
    const float* __restrict__ Whh, const float* __restrict__ bhh,
    const float* __restrict__ u, const float* __restrict__ Wpnf,
    const float* __restrict__ bpnf, const float* __restrict__ noise,
    float* __restrict__ out)
{
    extern __shared__ float sm[];
    const int bk = blockIdx.x;
    const int tid = threadIdx.x;
    const int lane = tid & 31;
    const int wp = tid >> 5;

    float* out_z  = out;
    float* out_mu = out + Bx * Wt * Zd;
    float* out_lv = out + 2 * Bx * Wt * Zd;
    const float u0 = u[0];

    if (bk < NHB) {
        float* s_whh = sm;
        float* s_red = sm + 24 * 1024;
        const int i0 = bk * 8;

        for (int idx = tid; idx < 24576; idx += 256) {
            int c = idx & 3;
            int rest = idx >> 2;
            int g = rest % 3;
            int t2 = rest / 3;
            int uu = t2 & 7;
            int kq = t2 >> 3;
            s_whh[idx] = Whh[(size_t)(g * Hd + i0 + uu) * Hd + kq * 4 + c];
        }
        __syncthreads();

        const int i = i0 + wp;
        const float bhr = bhh[i];
        const float bhz = bhh[Hd + i];
        const float bhn = bhh[2 * Hd + i];
        const int hoff = ((i >> 2) * 32 + lane) * 4 + (i & 3);
        const int kq0 = wp * 32;

        #pragma unroll 1
        for (int t = 0; t < Wt; t++) {
            if (tid == 0) {
                if (t > 0) wait_ge(&g_hprog, (unsigned)(NHB * t));
                if (t >= NSLOT) wait_ge(&g_zaprog, (unsigned)(NZB * (t - (NSLOT - 1))));
            }
            __syncthreads();

            const size_t gbase = ((size_t)t * G3) * 32;
            size_t o_r = gbase + (size_t)(0 * Hd + i) * 32 + lane;
            size_t o_z = gbase + (size_t)(1 * Hd + i) * 32 + lane;
            size_t o_n = gbase + (size_t)(2 * Hd + i) * 32 + lane;
            float gir = g_gi[o_r] + g_giB[o_r] + g_giC[o_r];
            float giz = g_gi[o_z] + g_giB[o_z] + g_giC[o_z];
            float gin = g_gi[o_n] + g_giB[o_n] + g_giC[o_n];
            const float* hb = g_hring + (size_t)(t & (NSLOT - 1)) * HB;
            float hold = ldcg_f(hb + hoff);

            unsigned long long acc[24];
            #pragma unroll
            for (int ug = 0; ug < 24; ug++) acc[ug] = 0ull;

            #pragma unroll 1
            for (int jb = 0; jb < 32; jb += 8) {
                ulonglong2 hv[8];
                #pragma unroll
                for (int j = 0; j < 8; j++)
                    hv[j] = ldcg_u2(hb + (size_t)((kq0 + jb + j) * 32 + lane) * 4);
                #pragma unroll
                for (int j = 0; j < 8; j++) {
                    const ulonglong2* wq = (const ulonglong2*)(s_whh + (size_t)(kq0 + jb + j) * 96);
                    #pragma unroll
                    for (int ug = 0; ug < 24; ug++) {
                        ulonglong2 w2 = wq[ug];
                        fma2(acc[ug], hv[j].x, w2.x);
                        fma2(acc[ug], hv[j].y, w2.y);
                    }
                }
            }
            #pragma unroll
            for (int ug = 0; ug < 24; ug++) {
                float2 p = unpack2(acc[ug]);
                s_red[(wp * 24 + ug) * 32 + lane] = p.x + p.y;
            }
            __syncthreads();

            float ar = 0.f, az = 0.f, an = 0.f;
            #pragma unroll
            for (int ww = 0; ww < 8; ww++) {
                ar += s_red[(ww * 24 + wp * 3 + 0) * 32 + lane];
                az += s_red[(ww * 24 + wp * 3 + 1) * 32 + lane];
                an += s_red[(ww * 24 + wp * 3 + 2) * 32 + lane];
            }
            float rg = 1.f / (1.f + expf(-(gir + ar + bhr)));
            float zg = 1.f / (1.f + expf(-(giz + az + bhz)));
            float ng = tanhf(gin + rg * (an + bhn));
            float hnew = (1.f - zg) * ng + zg * hold;
            stcg_f(g_hring + (size_t)((t + 1) & (NSLOT - 1)) * HB + hoff, hnew);

            __syncthreads();
            if (tid == 0) arrive(&g_hprog);
        }
    } else {
        const int zb = bk - NHB;
        const int q = zb * 8 + wp;
        const bool qa = (q < Zd);
        float* s_wm = sm + wp * 2272;
        float* s_ws = s_wm + 1136;
        float* s_pnf = sm + 8 * 2272 + wp * 104;

        if (qa) {
            for (int j = lane; j < ZH; j += 32) {
                s_wm[j] = g_Wmd[q * ZH + j];
                s_ws[j] = g_Wsd[q * ZH + j];
            }
            for (int j = lane; j < Zd; j += 32) s_pnf[j] = Wpnf[q * Zd + j];
        }
        __syncthreads();

        const float bm2 = qa ? g_bmu2[q] : 0.f;
        const float bs2 = qa ? g_bsig2[q] : 0.f;
        const float bpq = qa ? bpnf[q] : 0.f;
        const ulonglong2* wm2 = (const ulonglong2*)(s_wm + 100);
        const ulonglong2* ws2 = (const ulonglong2*)(s_ws + 100);

        #pragma unroll 1
        for (int t = 0; t < Wt; t++) {
            if (tid == 0) {
                wait_ge(&g_hprog, (unsigned)(NHB * (t + 1)));
                if (t > 0) wait_ge(&g_zbprog, (unsigned)(NZB * t));
            }
            __syncthreads();

            float zp = 0.f;
            if (qa) {
                float amz = 0.f, asz = 0.f;
                #pragma unroll 4
                for (int z2 = 0; z2 < Zd; z2++) {
                    float zv = ldcg_f(g_zT + z2 * 32 + lane);
                    amz = fmaf(zv, s_wm[z2], amz);
                    asz = fmaf(zv, s_ws[z2], asz);
                }
                const float* hb = g_hring + (size_t)((t + 1) & (NSLOT - 1)) * HB;
                unsigned long long am0 = 0, am1 = 0, as0 = 0, as1 = 0;
                #pragma unroll 1
                for (int c = 0; c < 256; c += 16) {
                    ulonglong2 hv[16];
                    #pragma unroll
                    for (int j = 0; j < 16; j++)
                        hv[j] = ldcg_u2(hb + (size_t)((c + j) * 32 + lane) * 4);
                    #pragma unroll
                    for (int j = 0; j < 16; j++) {
                        ulonglong2 m2 = wm2[c + j];
                        ulonglong2 s2 = ws2[c + j];
                        fma2(am0, hv[j].x, m2.x); fma2(am1, hv[j].y, m2.y);
                        fma2(as0, hv[j].x, s2.x); fma2(as1, hv[j].y, s2.y);
                    }
                }
                float m = bm2 + amz + hsum2(am0, am1);
                float s = bs2 + asz + hsum2(as0, as1);
                float lv = fmaxf(s, 0.f) + log1pf(expf(-fabsf(s)));
                float eps = noise[(size_t)(t * Bx + lane) * Zd + q];
                zp = m + expf(0.5f * lv) * eps;
                stcg_f(g_zpreT + q * 32 + lane, zp);
                out_mu[(size_t)(lane * Wt + t) * Zd + q] = m;
                out_lv[(size_t)(lane * Wt + t) * Zd + q] = lv;
            }
            __syncthreads();
            if (tid == 0) {
                arrive(&g_zaprog);
                wait_ge(&g_zaprog, (unsigned)(NZB * (t + 1)));
            }
            __syncthreads();

            if (qa) {
                float a0 = 0.f, a1 = 0.f;
                #pragma unroll 4
                for (int z2 = 0; z2 < Zd; z2 += 2) {
                    a0 = fmaf(ldcg_f(g_zpreT + (z2 + 0) * 32 + lane), s_pnf[z2 + 0], a0);
                    a1 = fmaf(ldcg_f(g_zpreT + (z2 + 1) * 32 + lane), s_pnf[z2 + 1], a1);
                }
                float zn = zp + u0 * tanhf((a0 + a1) + bpq);
                out_z[(size_t)(lane * Wt + t) * Zd + q] = zn;
                stcg_f(g_zT + q * 32 + lane, zn);
            }
            __syncthreads();
            if (tid == 0) arrive(&g_zbprog);
        }
    }
}

// ---------------- launch ----------------
extern "C" void kernel_launch(void* const* d_in, const int* in_sizes, int n_in,
                              void* d_out, int out_size)
{
    const float* x    = (const float*)d_in[0];
    const float* Wih  = (const float*)d_in[1];
    const float* Whh  = (const float*)d_in[2];
    const float* bih  = (const float*)d_in[3];
    const float* bhh  = (const float*)d_in[4];
    const float* Wd   = (const float*)d_in[5];
    const float* bd   = (const float*)d_in[6];
    const float* Wmu  = (const float*)d_in[7];
    const float* bmu  = (const float*)d_in[8];
    const float* Wsig = (const float*)d_in[9];
    const float* bsig = (const float*)d_in[10];
    const float* u    = (const float*)d_in[11];
    const float* Wpnf = (const float*)d_in[12];
    const float* bpnf = (const float*)d_in[13];
    const float* noise= (const float*)d_in[14];
    float* out = (float*)d_out;

    cudaFuncSetAttribute(recur2, cudaFuncAttributeMaxDynamicSharedMemorySize, SMEM_BYTES);
    cudaFuncSetAttribute(gemm_mma, cudaFuncAttributeMaxDynamicSharedMemorySize, GEMM_SMEM);

    prep_kernel<<<(Zd * ZH + 255) / 256, 256>>>(Wd, bd, Wmu, bmu, Wsig, bsig);
    conv_x<<<(8192 * 4096) / (8 * 256), 256>>>(x);
    conv_w<<<(3072 * 4096) / (8 * 256), 256>>>(Wih);
    gemm_mma<<<GRID_P, 256, GEMM_SMEM>>>(bih);
    recur2<<<NHB + NZB, 256, SMEM_BYTES>>>(Whh, bhh, u, Wpnf, bpnf, noise, out);
}

// round 10
// speedup vs baseline: 3.6069x; 1.4534x over previous
#include <cuda_runtime.h>
#include <cuda_bf16.h>
#include <math.h>
#include <stdint.h>

#define Bx  32
#define Wt  256
#define IND 4096
#define Hd  1024
#define Zd  100
#define Dd  100
#define G3  3072
#define ZH  1124
#define NHB 128
#define NZB 13
#define HB  (Hd * Bx)
#define NSLOT 16

// ---------------- f32x2 packed-FMA helpers ----------------
__device__ __forceinline__ void fma2(unsigned long long& d, unsigned long long a, unsigned long long b) {
    asm("fma.rn.f32x2 %0, %1, %2, %0;" : "+l"(d) : "l"(a), "l"(b));
}
__device__ __forceinline__ float2 unpack2(unsigned long long v) {
    float2 r;
    asm("mov.b64 {%0, %1}, %2;" : "=f"(r.x), "=f"(r.y) : "l"(v));
    return r;
}
__device__ __forceinline__ float hsum2(unsigned long long a, unsigned long long b) {
    float2 p = unpack2(a), q = unpack2(b);
    return (p.x + p.y) + (q.x + q.y);
}

// ---------------- L2-coherent load/store + sync primitives ----------------
__device__ __forceinline__ ulonglong2 ldcg_u2(const void* p) {
    ulonglong2 v;
    asm volatile("ld.global.cg.v2.u64 {%0,%1},[%2];" : "=l"(v.x), "=l"(v.y) : "l"(p));
    return v;
}
__device__ __forceinline__ float ldcg_f(const float* p) {
    float v; asm volatile("ld.global.cg.f32 %0,[%1];" : "=f"(v) : "l"(p)); return v;
}
__device__ __forceinline__ void stcg_f(float* p, float v) {
    asm volatile("st.global.cg.f32 [%0],%1;" :: "l"(p), "f"(v));
}
__device__ __forceinline__ void arrive(unsigned* c) {
    asm volatile("red.release.gpu.global.add.u32 [%0],%1;" :: "l"(c), "r"(1u) : "memory");
}
__device__ __forceinline__ void wait_ge(const unsigned* c, unsigned target) {
    unsigned v;
    do {
        asm volatile("ld.acquire.gpu.global.u32 %0,[%1];" : "=r"(v) : "l"(c) : "memory");
    } while ((int)(v - target) < 0);
}

// ---------------- mma.sync helpers ----------------
__device__ __forceinline__ uint32_t smem_u32(const void* p) {
    uint32_t a;
    asm("{ .reg .u64 t; cvta.to.shared.u64 t, %1; cvt.u32.u64 %0, t; }" : "=r"(a) : "l"(p));
    return a;
}
__device__ __forceinline__ void ldsm4(uint32_t* r, uint32_t addr) {
    asm volatile("ldmatrix.sync.aligned.m8n8.x4.shared.b16 {%0,%1,%2,%3},[%4];"
                 : "=r"(r[0]), "=r"(r[1]), "=r"(r[2]), "=r"(r[3]) : "r"(addr));
}
__device__ __forceinline__ void mma16816(float* c, const uint32_t* a, const uint32_t* b) {
    asm volatile("mma.sync.aligned.m16n8k16.row.col.f32.bf16.bf16.f32 "
                 "{%0,%1,%2,%3},{%4,%5,%6,%7},{%8,%9},{%0,%1,%2,%3};"
                 : "+f"(c[0]), "+f"(c[1]), "+f"(c[2]), "+f"(c[3])
                 : "r"(a[0]), "r"(a[1]), "r"(a[2]), "r"(a[3]), "r"(b[0]), "r"(b[1]));
}
__device__ __forceinline__ void cp_async16(uint32_t saddr, const void* gaddr) {
    asm volatile("cp.async.cg.shared.global [%0],[%1],16;" :: "r"(saddr), "l"(gaddr));
}
#define CP_COMMIT() asm volatile("cp.async.commit_group;" ::: "memory")
#define CP_WAIT(n)  asm volatile("cp.async.wait_group %0;" :: "n"(n) : "memory")

// ---------------- device globals ----------------
__device__ __align__(16) float g_gi [25165824];       // pass0: xh*wh + bias   [W][3H][B]
__device__ __align__(16) float g_giB[25165824];       // pass1: xh*wl
__device__ __align__(16) float g_giC[25165824];       // pass2: xl*wh
__device__ __align__(16) __nv_bfloat16 g_xh[8192 * 4096];
__device__ __align__(16) __nv_bfloat16 g_xl[8192 * 4096];
__device__ __align__(16) __nv_bfloat16 g_wh[3072 * 4096];
__device__ __align__(16) __nv_bfloat16 g_wl[3072 * 4096];
__device__ __align__(16) float g_hring[NSLOT * HB];
__device__ __align__(16) float g_zT[Zd * Bx];
__device__ __align__(16) float g_zpreT[Zd * Bx];
__device__ __align__(16) float g_Wmd[Zd * ZH];
__device__ __align__(16) float g_Wsd[Zd * ZH];
__device__ float g_bmu2[Zd];
__device__ float g_bsig2[Zd];
__device__ unsigned g_hprog;
__device__ unsigned g_zaprog;
__device__ unsigned g_zbprog;

// ---------------- prep ----------------
__global__ void prep_kernel(const float* __restrict__ Wd, const float* __restrict__ bd,
                            const float* __restrict__ Wmu, const float* __restrict__ bmu,
                            const float* __restrict__ Wsig, const float* __restrict__ bsig)
{
    int idx = blockIdx.x * blockDim.x + threadIdx.x;
    if (idx < Zd * ZH) {
        int q = idx / ZH, j = idx % ZH;
        float am = 0.f, as = 0.f;
        for (int d = 0; d < Dd; d++) {
            float wd = Wd[(size_t)d * ZH + j];
            am = fmaf(Wmu[q * Dd + d], wd, am);
            as = fmaf(Wsig[q * Dd + d], wd, as);
        }
        g_Wmd[idx] = am;
        g_Wsd[idx] = as;
    }
    if (idx < Zd) {
        float am = bmu[idx], as = bsig[idx];
        for (int d = 0; d < Dd; d++) {
            am = fmaf(Wmu[idx * Dd + d], bd[d], am);
            as = fmaf(Wsig[idx * Dd + d], bd[d], as);
        }
        g_bmu2[idx] = am;
        g_bsig2[idx] = as;
    }
    if (idx < HB) g_hring[idx] = 0.f;
    if (idx < Zd * Bx) g_zT[idx] = 0.f;
    if (idx == 0) { g_hprog = 0u; g_zaprog = 0u; g_zbprog = 0u; }
}

// ---------------- split conversions ----------------
__device__ __forceinline__ void split8(const float* s, __nv_bfloat16* h, __nv_bfloat16* l) {
    #pragma unroll
    for (int i = 0; i < 8; i++) {
        float v = s[i];
        __nv_bfloat16 hb = __float2bfloat16_rn(v);
        h[i] = hb;
        l[i] = __float2bfloat16_rn(v - __bfloat162float(hb));
    }
}

__global__ void __launch_bounds__(256) conv_x(const float* __restrict__ x) {
    size_t idx = ((size_t)blockIdx.x * 256 + threadIdx.x) * 8;
    int m = (int)(idx >> 12), k = (int)(idx & 4095);
    int b = m & 31, w = m >> 5;
    float s[8];
    *(float4*)(s)     = *(const float4*)(x + ((size_t)(b * Wt + w) << 12) + k);
    *(float4*)(s + 4) = *(const float4*)(x + ((size_t)(b * Wt + w) << 12) + k + 4);
    __nv_bfloat16 h[8], l[8];
    split8(s, h, l);
    *(uint4*)(g_xh + idx) = *(uint4*)h;
    *(uint4*)(g_xl + idx) = *(uint4*)l;
}

__global__ void __launch_bounds__(256) conv_w(const float* __restrict__ Wih) {
    size_t idx = ((size_t)blockIdx.x * 256 + threadIdx.x) * 8;
    float s[8];
    *(float4*)(s)     = *(const float4*)(Wih + idx);
    *(float4*)(s + 4) = *(const float4*)(Wih + idx + 4);
    __nv_bfloat16 h[8], l[8];
    split8(s, h, l);
    *(uint4*)(g_wh + idx) = *(uint4*)h;
    *(uint4*)(g_wl + idx) = *(uint4*)l;
}

// ---------------- persistent mma.sync GEMM over (tile, pass) work items ----------------
#define NITEM 4608
#define GRID_P 296
#define STG64 32768
#define SMB_B64 16384
#define GEMM_SMEM (3 * STG64)     // 96KB

__global__ void __launch_bounds__(256, 2) gemm_mma(const float* __restrict__ bih) {
    extern __shared__ __align__(128) char smg[];
    const uint32_t sbase = smem_u32(smg);
    const int tid = threadIdx.x;
    const int lane = tid & 31;
    const int wid = tid >> 5;
    const int wm = (wid & 3) * 32;
    const int wn = (wid >> 2) * 64;

    auto sw = [](int r, int cb) -> uint32_t {
        return (uint32_t)(r * 128 + ((cb ^ (r & 7)) << 4));
    };

    uint32_t aoff[2][4], boff[4][4];
    {
        int ml = wm + (lane & 15);
        #pragma unroll
        for (int mt = 0; mt < 2; mt++)
            #pragma unroll
            for (int kh = 0; kh < 4; kh++)
                aoff[mt][kh] = sw(ml + mt * 16, kh * 2 + (lane >> 4));
        int nl = wn + ((lane >> 4) << 3) + (lane & 7);
        #pragma unroll
        for (int p = 0; p < 4; p++)
            #pragma unroll
            for (int kh = 0; kh < 4; kh++)
                boff[p][kh] = (uint32_t)SMB_B64 + sw(nl + p * 16, kh * 2 + ((lane >> 3) & 1));
    }

    #pragma unroll 1
    for (int j = blockIdx.x; j < NITEM; j += GRID_P) {
        const int pass = j / 1536;
        const int rem  = j % 1536;
        const int tm   = rem / 24;
        const int tn   = rem % 24;
        const __nv_bfloat16* Asrc = (pass < 2) ? g_xh : g_xl;
        const __nv_bfloat16* Bsrc = (pass == 1) ? g_wl : g_wh;

        auto load_st = [&](int it, int slot) {
            int k0 = it << 6;
            uint32_t sb = sbase + slot * STG64;
            #pragma unroll
            for (int i = 0; i < 4; i++) {
                int idx = tid + i * 256;
                int r = idx >> 3, cb = idx & 7;
                cp_async16(sb + sw(r, cb), Asrc + (((size_t)(tm * 128 + r)) << 12) + k0 + cb * 8);
            }
            #pragma unroll
            for (int i = 0; i < 4; i++) {
                int idx = tid + i * 256;
                int r = idx >> 3, cb = idx & 7;
                cp_async16(sb + SMB_B64 + sw(r, cb), Bsrc + (((size_t)(tn * 128 + r)) << 12) + k0 + cb * 8);
            }
            CP_COMMIT();
        };

        float acc[2][8][4];
        #pragma unroll
        for (int mt = 0; mt < 2; mt++)
            #pragma unroll
            for (int nt = 0; nt < 8; nt++)
                #pragma unroll
                for (int e = 0; e < 4; e++) acc[mt][nt][e] = 0.f;

        __syncthreads();
        load_st(0, 0);
        load_st(1, 1);

        #pragma unroll 1
        for (int it = 0; it < 64; it++) {
            if (it >= 62) { CP_WAIT(0); } else { CP_WAIT(1); }
            __syncthreads();
            int slot = it % 3;
            uint32_t sb = sbase + slot * STG64;
            #pragma unroll
            for (int kh = 0; kh < 4; kh++) {
                uint32_t a[2][4], b[4][4];
                ldsm4(a[0], sb + aoff[0][kh]);
                ldsm4(a[1], sb + aoff[1][kh]);
                #pragma unroll
                for (int p = 0; p < 4; p++) ldsm4(b[p], sb + boff[p][kh]);
                #pragma unroll
                for (int mt = 0; mt < 2; mt++)
                    #pragma unroll
                    for (int nt = 0; nt < 8; nt++)
                        mma16816(acc[mt][nt], a[mt], &b[nt >> 1][(nt & 1) * 2]);
            }
            if (it + 2 < 64) load_st(it + 2, (it + 2) % 3);
        }

        float* gout = (pass == 0) ? g_gi : ((pass == 1) ? g_giB : g_giC);
        #pragma unroll
        for (int mt = 0; mt < 2; mt++) {
            int row0 = tm * 128 + wm + mt * 16 + (lane >> 2);
            #pragma unroll
            for (int half = 0; half < 2; half++) {
                int row = row0 + half * 8;
                int w = row >> 5, b = row & 31;
                float* orow = gout + (size_t)w * G3 * 32 + b;
                #pragma unroll
                for (int nt = 0; nt < 8; nt++) {
                    int n = tn * 128 + wn + nt * 8 + (lane & 3) * 2;
                    float bia0 = (pass == 0) ? __ldg(bih + n) : 0.f;
                    float bia1 = (pass == 0) ? __ldg(bih + n + 1) : 0.f;
                    orow[(size_t)n * 32]       = acc[mt][nt][half * 2 + 0] + bia0;
                    orow[(size_t)(n + 1) * 32] = acc[mt][nt][half * 2 + 1] + bia1;
                }
            }
        }
    }
}

// ---------------- split-pipeline recurrence ----------------
// h-CTAs (0..127): k-split GRU GEMV (unchanged).
// z-CTAs (128..140): NOW k-split across warps too — warp wp accumulates kq-slice
// [32wp,32wp+32) for all 8 q's x 2 heads (16 packed accumulators); smem reduce;
// owner warp wp finalizes q = zb*8+wp.
#define SMEM_BYTES ((24 * 1024 + 6 * 1024) * 4)

__global__ void __launch_bounds__(256, 1) recur2(
    const float* __restrict__ Whh, const float* __restrict__ bhh,
    const float* __restrict__ u, const float* __restrict__ Wpnf,
    const float* __restrict__ bpnf, const float* __restrict__ noise,
    float* __restrict__ out)
{
    extern __shared__ float sm[];
    const int bk = blockIdx.x;
    const int tid = threadIdx.x;
    const int lane = tid & 31;
    const int wp = tid >> 5;

    float* out_z  = out;
    float* out_mu = out + Bx * Wt * Zd;
    float* out_lv = out + 2 * Bx * Wt * Zd;
    const float u0 = u[0];

    if (bk < NHB) {
        float* s_whh = sm;
        float* s_red = sm + 24 * 1024;
        const int i0 = bk * 8;

        for (int idx = tid; idx < 24576; idx += 256) {
            int c = idx & 3;
            int rest = idx >> 2;
            int g = rest % 3;
            int t2 = rest / 3;
            int uu = t2 & 7;
            int kq = t2 >> 3;
            s_whh[idx] = Whh[(size_t)(g * Hd + i0 + uu) * Hd + kq * 4 + c];
        }
        __syncthreads();

        const int i = i0 + wp;
        const float bhr = bhh[i];
        const float bhz = bhh[Hd + i];
        const float bhn = bhh[2 * Hd + i];
        const int hoff = ((i >> 2) * 32 + lane) * 4 + (i & 3);
        const int kq0 = wp * 32;

        #pragma unroll 1
        for (int t = 0; t < Wt; t++) {
            if (tid == 0) {
                if (t > 0) wait_ge(&g_hprog, (unsigned)(NHB * t));
                if (t >= NSLOT) wait_ge(&g_zaprog, (unsigned)(NZB * (t - (NSLOT - 1))));
            }
            __syncthreads();

            const size_t gbase = ((size_t)t * G3) * 32;
            size_t o_r = gbase + (size_t)(0 * Hd + i) * 32 + lane;
            size_t o_z = gbase + (size_t)(1 * Hd + i) * 32 + lane;
            size_t o_n = gbase + (size_t)(2 * Hd + i) * 32 + lane;
            float gir = g_gi[o_r] + g_giB[o_r] + g_giC[o_r];
            float giz = g_gi[o_z] + g_giB[o_z] + g_giC[o_z];
            float gin = g_gi[o_n] + g_giB[o_n] + g_giC[o_n];
            const float* hb = g_hring + (size_t)(t & (NSLOT - 1)) * HB;
            float hold = ldcg_f(hb + hoff);

            unsigned long long acc[24];
            #pragma unroll
            for (int ug = 0; ug < 24; ug++) acc[ug] = 0ull;

            #pragma unroll 1
            for (int jb = 0; jb < 32; jb += 8) {
                ulonglong2 hv[8];
                #pragma unroll
                for (int j = 0; j < 8; j++)
                    hv[j] = ldcg_u2(hb + (size_t)((kq0 + jb + j) * 32 + lane) * 4);
                #pragma unroll
                for (int j = 0; j < 8; j++) {
                    const ulonglong2* wq = (const ulonglong2*)(s_whh + (size_t)(kq0 + jb + j) * 96);
                    #pragma unroll
                    for (int ug = 0; ug < 24; ug++) {
                        ulonglong2 w2 = wq[ug];
                        fma2(acc[ug], hv[j].x, w2.x);
                        fma2(acc[ug], hv[j].y, w2.y);
                    }
                }
            }
            #pragma unroll
            for (int ug = 0; ug < 24; ug++) {
                float2 p = unpack2(acc[ug]);
                s_red[(wp * 24 + ug) * 32 + lane] = p.x + p.y;
            }
            __syncthreads();

            float ar = 0.f, az = 0.f, an = 0.f;
            #pragma unroll
            for (int ww = 0; ww < 8; ww++) {
                ar += s_red[(ww * 24 + wp * 3 + 0) * 32 + lane];
                az += s_red[(ww * 24 + wp * 3 + 1) * 32 + lane];
                an += s_red[(ww * 24 + wp * 3 + 2) * 32 + lane];
            }
            float rg = 1.f / (1.f + expf(-(gir + ar + bhr)));
            float zg = 1.f / (1.f + expf(-(giz + az + bhz)));
            float ng = tanhf(gin + rg * (an + bhn));
            float hnew = (1.f - zg) * ng + zg * hold;
            stcg_f(g_hring + (size_t)((t + 1) & (NSLOT - 1)) * HB + hoff, hnew);

            __syncthreads();
            if (tid == 0) arrive(&g_hprog);
        }
    } else {
        // ---------------- z-pipeline CTA, k-split ----------------
        const int zb = bk - NHB;           // 0..12
        const int q0 = zb * 8;
        float* s_wz  = sm;                              // [256 kq][16 ug][4] = 16384 floats
        float* s_wzz = sm + 16384;                      // [100 z2][16 ug]    = 1600
        float* s_pnf = sm + 16384 + 1600;               // [8 q8][104]        = 832
        float* s_red = sm + 16384 + 1600 + 832;         // [8 wp][16 ug][32]  = 4096

        for (int idx = tid; idx < 8 * ZH; idx += 256) {
            int q8 = idx / ZH, jj = idx % ZH;
            int q = q0 + q8;
            float wm = (q < Zd) ? g_Wmd[(size_t)q * ZH + jj] : 0.f;
            float ws = (q < Zd) ? g_Wsd[(size_t)q * ZH + jj] : 0.f;
            if (jj < Zd) {
                s_wzz[jj * 16 + q8 * 2 + 0] = wm;
                s_wzz[jj * 16 + q8 * 2 + 1] = ws;
            } else {
                int kk = jj - Zd;
                int kq = kk >> 2, c = kk & 3;
                s_wz[(kq * 16 + q8 * 2 + 0) * 4 + c] = wm;
                s_wz[(kq * 16 + q8 * 2 + 1) * 4 + c] = ws;
            }
        }
        for (int idx = tid; idx < 8 * Zd; idx += 256) {
            int q8 = idx / Zd, z2 = idx % Zd;
            int q = q0 + q8;
            s_pnf[q8 * 104 + z2] = (q < Zd) ? Wpnf[q * Zd + z2] : 0.f;
        }
        __syncthreads();

        const int q = q0 + wp;             // warp wp owns/finalizes this z-index
        const bool qa = (q < Zd);
        const float bm2 = qa ? g_bmu2[q] : 0.f;
        const float bs2 = qa ? g_bsig2[q] : 0.f;
        const float bpq = qa ? bpnf[q] : 0.f;
        const int kq0 = wp * 32;

        #pragma unroll 1
        for (int t = 0; t < Wt; t++) {
            if (tid == 0) {
                wait_ge(&g_hprog, (unsigned)(NHB * (t + 1)));
                if (t > 0) wait_ge(&g_zbprog, (unsigned)(NZB * t));
            }
            __syncthreads();

            // k-split partials for all 16 (q8, head)
            float zacc[16];
            #pragma unroll
            for (int ug = 0; ug < 16; ug++) zacc[ug] = 0.f;
            for (int z2 = wp; z2 < Zd; z2 += 8) {
                float zv = ldcg_f(g_zT + z2 * 32 + lane);
                #pragma unroll
                for (int ug = 0; ug < 16; ug++)
                    zacc[ug] = fmaf(zv, s_wzz[z2 * 16 + ug], zacc[ug]);
            }

            const float* hb = g_hring + (size_t)((t + 1) & (NSLOT - 1)) * HB;
            unsigned long long acc[16];
            #pragma unroll
            for (int ug = 0; ug < 16; ug++) acc[ug] = 0ull;

            #pragma unroll 1
            for (int jb = 0; jb < 32; jb += 8) {
                ulonglong2 hv[8];
                #pragma unroll
                for (int j = 0; j < 8; j++)
                    hv[j] = ldcg_u2(hb + (size_t)((kq0 + jb + j) * 32 + lane) * 4);
                #pragma unroll
                for (int j = 0; j < 8; j++) {
                    const ulonglong2* wq = (const ulonglong2*)(s_wz + (size_t)(kq0 + jb + j) * 64);
                    #pragma unroll
                    for (int ug = 0; ug < 16; ug++) {
                        ulonglong2 w2 = wq[ug];
                        fma2(acc[ug], hv[j].x, w2.x);
                        fma2(acc[ug], hv[j].y, w2.y);
                    }
                }
            }
            #pragma unroll
            for (int ug = 0; ug < 16; ug++) {
                float2 p = unpack2(acc[ug]);
                s_red[(wp * 16 + ug) * 32 + lane] = zacc[ug] + p.x + p.y;
            }
            __syncthreads();

            float zp = 0.f;
            if (qa) {
                float m = bm2, s = bs2;
                #pragma unroll
                for (int ww = 0; ww < 8; ww++) {
                    m += s_red[(ww * 16 + wp * 2 + 0) * 32 + lane];
                    s += s_red[(ww * 16 + wp * 2 + 1) * 32 + lane];
                }
                float lv = fmaxf(s, 0.f) + log1pf(expf(-fabsf(s)));
                float eps = noise[(size_t)(t * Bx + lane) * Zd + q];
                zp = m + expf(0.5f * lv) * eps;
                stcg_f(g_zpreT + q * 32 + lane, zp);
                out_mu[(size_t)(lane * Wt + t) * Zd + q] = m;
                out_lv[(size_t)(lane * Wt + t) * Zd + q] = lv;
            }
            __syncthreads();
            if (tid == 0) {
                arrive(&g_zaprog);
                wait_ge(&g_zaprog, (unsigned)(NZB * (t + 1)));
            }
            __syncthreads();

            if (qa) {
                const float* pnf = s_pnf + wp * 104;
                float a0 = 0.f, a1 = 0.f;
                #pragma unroll 4
                for (int z2 = 0; z2 < Zd; z2 += 2) {
                    a0 = fmaf(ldcg_f(g_zpreT + (z2 + 0) * 32 + lane), pnf[z2 + 0], a0);
                    a1 = fmaf(ldcg_f(g_zpreT + (z2 + 1) * 32 + lane), pnf[z2 + 1], a1);
                }
                float zn = zp + u0 * tanhf((a0 + a1) + bpq);
                out_z[(size_t)(lane * Wt + t) * Zd + q] = zn;
                stcg_f(g_zT + q * 32 + lane, zn);
            }
            __syncthreads();
            if (tid == 0) arrive(&g_zbprog);
        }
    }
}

// ---------------- launch ----------------
extern "C" void kernel_launch(void* const* d_in, const int* in_sizes, int n_in,
                              void* d_out, int out_size)
{
    const float* x    = (const float*)d_in[0];
    const float* Wih  = (const float*)d_in[1];
    const float* Whh  = (const float*)d_in[2];
    const float* bih  = (const float*)d_in[3];
    const float* bhh  = (const float*)d_in[4];
    const float* Wd   = (const float*)d_in[5];
    const float* bd   = (const float*)d_in[6];
    const float* Wmu  = (const float*)d_in[7];
    const float* bmu  = (const float*)d_in[8];
    const float* Wsig = (const float*)d_in[9];
    const float* bsig = (const float*)d_in[10];
    const float* u    = (const float*)d_in[11];
    const float* Wpnf = (const float*)d_in[12];
    const float* bpnf = (const float*)d_in[13];
    const float* noise= (const float*)d_in[14];
    float* out = (float*)d_out;

    cudaFuncSetAttribute(recur2, cudaFuncAttributeMaxDynamicSharedMemorySize, SMEM_BYTES);
    cudaFuncSetAttribute(gemm_mma, cudaFuncAttributeMaxDynamicSharedMemorySize, GEMM_SMEM);

    prep_kernel<<<(Zd * ZH + 255) / 256, 256>>>(Wd, bd, Wmu, bmu, Wsig, bsig);
    conv_x<<<(8192 * 4096) / (8 * 256), 256>>>(x);
    conv_w<<<(3072 * 4096) / (8 * 256), 256>>>(Wih);
    gemm_mma<<<GRID_P, 256, GEMM_SMEM>>>(bih);
    recur2<<<NHB + NZB, 256, SMEM_BYTES>>>(Whh, bhh, u, Wpnf, bpnf, noise, out);
}